// round 3
// baseline (speedup 1.0000x reference)
#include <cuda_runtime.h>
#include <math.h>

// Problem constants
#define MM   8192        // bs*n
#define DD   768         // feature dim
#define KD   64          // Psi dim
#define KF   32          // feature top-k
#define HW   1024        // pixels per image
#define BSZ  8           // batch

// -------- device scratch (static, no runtime alloc) --------
__device__ float g_Xn[(size_t)MM*DD];            // normalized features  (25 MB)
__device__ float g_A[(size_t)MM*MM];             // clamped sim matrix   (268 MB)
__device__ float g_topv[MM*KF];
__device__ int   g_topi[MM*KF];
__device__ float g_deg[MM];
__device__ float g_drs[MM];
__device__ unsigned char g_adj[(size_t)BSZ*HW*HW];  // pixel adjacency (8.4 MB)
__device__ float g_deg2[MM];
__device__ float g_drs2[MM];
__device__ float g_gP[MM*KD];                    // gram_total @ Psi (sparse accumulated)
__device__ float g_R[KD*KD];

// -------- zero scratch that accumulates --------
__global__ void zero_kernel() {
    int idx = blockIdx.x * blockDim.x + threadIdx.x;
    int n   = gridDim.x * blockDim.x;
    for (int i = idx; i < MM; i += n) { g_deg[i] = 0.f; g_deg2[i] = 0.f; }
    for (int i = idx; i < MM*KD; i += n) g_gP[i] = 0.f;
    for (int i = idx; i < KD*KD; i += n) g_R[i] = 0.f;
    unsigned int* aj = (unsigned int*)g_adj;
    for (int i = idx; i < (int)((size_t)BSZ*HW*HW/4); i += n) aj[i] = 0u;
}

// -------- row-normalize features (1 warp / row) --------
__global__ void normalize_kernel(const float* __restrict__ hf) {
    int row  = blockIdx.x * 8 + (threadIdx.x >> 5);
    int lane = threadIdx.x & 31;
    const float* x = hf + (size_t)row * DD;
    float s = 0.f;
    for (int k = lane; k < DD; k += 32) { float v = x[k]; s += v * v; }
    #pragma unroll
    for (int o = 16; o > 0; o >>= 1) s += __shfl_xor_sync(0xffffffffu, s, o);
    float inv = 1.0f / sqrtf(s);
    float* y = g_Xn + (size_t)row * DD;
    for (int k = lane; k < DD; k += 32) y[k] = x[k] * inv;
}

// -------- symmetric SGEMM with packed f32x2 FFMA: A = clamp(Xn Xn^T) --------
__global__ __launch_bounds__(256) void gemm_sym_kernel() {
    int t  = blockIdx.x;
    int bc = (int)((sqrtf(8.0f * (float)t + 1.0f) - 1.0f) * 0.5f);
    while ((bc + 1) * (bc + 2) / 2 <= t) bc++;
    while (bc * (bc + 1) / 2 > t) bc--;
    int br = t - bc * (bc + 1) / 2;          // br <= bc

    __shared__ float As[16][132];
    __shared__ float Bs[16][132];

    int tid = threadIdx.x;
    int r   = tid >> 2, kq = tid & 3;        // loader mapping
    int tx  = tid & 15, ty = tid >> 4;       // compute mapping (16x16 threads, 8x8 each)

    const float* Abase = g_Xn + (size_t)(br * 128) * DD;
    const float* Bbase = g_Xn + (size_t)(bc * 128) * DD;

    // packed accumulators: acc2[m][n] covers columns (2n, 2n+1)
    unsigned long long acc2[8][4];
    #pragma unroll
    for (int m = 0; m < 8; m++)
        #pragma unroll
        for (int n = 0; n < 4; n++) acc2[m][n] = 0ull;

    for (int k0 = 0; k0 < DD; k0 += 16) {
        float4 a0 = *(const float4*)(Abase + (size_t)r        * DD + k0 + kq * 4);
        float4 a1 = *(const float4*)(Abase + (size_t)(r + 64) * DD + k0 + kq * 4);
        float4 b0 = *(const float4*)(Bbase + (size_t)r        * DD + k0 + kq * 4);
        float4 b1 = *(const float4*)(Bbase + (size_t)(r + 64) * DD + k0 + kq * 4);
        __syncthreads();
        As[kq*4+0][r] = a0.x; As[kq*4+1][r] = a0.y; As[kq*4+2][r] = a0.z; As[kq*4+3][r] = a0.w;
        As[kq*4+0][r+64] = a1.x; As[kq*4+1][r+64] = a1.y; As[kq*4+2][r+64] = a1.z; As[kq*4+3][r+64] = a1.w;
        Bs[kq*4+0][r] = b0.x; Bs[kq*4+1][r] = b0.y; Bs[kq*4+2][r] = b0.z; Bs[kq*4+3][r] = b0.w;
        Bs[kq*4+0][r+64] = b1.x; Bs[kq*4+1][r+64] = b1.y; Bs[kq*4+2][r+64] = b1.z; Bs[kq*4+3][r+64] = b1.w;
        __syncthreads();
        #pragma unroll
        for (int kk = 0; kk < 16; kk++) {
            float a[8], b[8];
            *(float4*)&a[0] = *(const float4*)&As[kk][ty * 8];
            *(float4*)&a[4] = *(const float4*)&As[kk][ty * 8 + 4];
            *(float4*)&b[0] = *(const float4*)&Bs[kk][tx * 8];
            *(float4*)&b[4] = *(const float4*)&Bs[kk][tx * 8 + 4];
            unsigned long long bp[4];
            #pragma unroll
            for (int n = 0; n < 4; n++)
                asm("mov.b64 %0, {%1, %2};" : "=l"(bp[n])
                    : "r"(__float_as_uint(b[2*n])), "r"(__float_as_uint(b[2*n+1])));
            #pragma unroll
            for (int m = 0; m < 8; m++) {
                unsigned long long ap;
                asm("mov.b64 %0, {%1, %1};" : "=l"(ap) : "r"(__float_as_uint(a[m])));
                #pragma unroll
                for (int n = 0; n < 4; n++)
                    asm("fma.rn.f32x2 %0, %1, %2, %0;" : "+l"(acc2[m][n]) : "l"(ap), "l"(bp[n]));
            }
        }
    }

    #pragma unroll
    for (int m = 0; m < 8; m++) {
        int i = br * 128 + ty * 8 + m;
        #pragma unroll
        for (int n = 0; n < 4; n++) {
            unsigned int lo, hi;
            asm("mov.b64 {%0, %1}, %2;" : "=r"(lo), "=r"(hi) : "l"(acc2[m][n]));
            float v0 = __uint_as_float(lo);
            float v1 = __uint_as_float(hi);
            int j0 = bc * 128 + tx * 8 + 2*n;
            int j1 = j0 + 1;
            v0 = (i == j0) ? 0.0f : fmaxf(v0, 0.0f);
            v1 = (i == j1) ? 0.0f : fmaxf(v1, 0.0f);
            g_A[(size_t)i * MM + j0] = v0;
            g_A[(size_t)j0 * MM + i] = v0;
            g_A[(size_t)i * MM + j1] = v1;
            g_A[(size_t)j1 * MM + i] = v1;
        }
    }
}

// -------- per-row top-32: register-resident incremental argmax --------
// Thread t owns elements j = t + 256*i (i=0..31), kept in registers.
// Per iteration: warp shuffle reduce -> 8 leaders -> warp-0 reduce -> broadcast;
// only the winning thread removes its element and recomputes its local max.
__global__ __launch_bounds__(256) void topk_kernel() {
    int row = blockIdx.x;
    __shared__ float wv[8];
    __shared__ int   wi[8];
    __shared__ float sbv_s;
    __shared__ int   sbi_s;
    int tid = threadIdx.x;
    const float* arow = g_A + (size_t)row * MM;

    float lval[32];
    float lv = -1.0f; int li = MM;
    #pragma unroll
    for (int i = 0; i < 32; i++) {
        float v = arow[tid + (i << 8)];
        lval[i] = v;
        if (v > lv) { lv = v; li = tid + (i << 8); }  // strict > => lowest j wins
    }

    for (int it = 0; it < KF; it++) {
        float v = lv; int idx = li;
        #pragma unroll
        for (int o = 16; o > 0; o >>= 1) {
            float ov = __shfl_xor_sync(0xffffffffu, v, o);
            int   oi = __shfl_xor_sync(0xffffffffu, idx, o);
            if (ov > v || (ov == v && oi < idx)) { v = ov; idx = oi; }
        }
        if ((tid & 31) == 0) { wv[tid >> 5] = v; wi[tid >> 5] = idx; }
        __syncthreads();
        if (tid < 8) {
            float v8 = wv[tid]; int i8 = wi[tid];
            #pragma unroll
            for (int o = 4; o > 0; o >>= 1) {
                float ov = __shfl_xor_sync(0x000000ffu, v8, o);
                int   oi = __shfl_xor_sync(0x000000ffu, i8, o);
                if (ov > v8 || (ov == v8 && oi < i8)) { v8 = ov; i8 = oi; }
            }
            if (tid == 0) {
                g_topv[row * KF + it] = v8;
                g_topi[row * KF + it] = i8;
                sbv_s = v8; sbi_s = i8;
            }
        }
        __syncthreads();
        int win = sbi_s;
        if ((win & 255) == tid) {
            int slot = win >> 8;
            #pragma unroll
            for (int i = 0; i < 32; i++)
                if (i == slot) lval[i] = -1.0f;       // predicated removal, stays in regs
            lv = -1.0f; li = MM;
            #pragma unroll
            for (int i = 0; i < 32; i++) {
                if (lval[i] > lv) { lv = lval[i]; li = tid + (i << 8); }
            }
        }
        __syncthreads();
    }
}

// -------- feature degrees: deg = rowsum((res+res^T)/2) --------
__global__ void feat_deg_kernel() {
    int e = blockIdx.x * blockDim.x + threadIdx.x;
    if (e >= MM * KF) return;
    int i = e >> 5; int j = g_topi[e]; float v = g_topv[e];
    atomicAdd(&g_deg[i], 0.5f * v);
    atomicAdd(&g_deg[j], 0.5f * v);
}

// -------- pixel adjacency: per (batch,row) top-10 for both (k,dw) configs --------
__global__ __launch_bounds__(256) void pixel_adj_kernel(const float* __restrict__ im) {
    int blk = blockIdx.x; int b = blk >> 10; int i = blk & 1023;
    int tid = threadIdx.x;
    __shared__ float sf[3][HW];
    __shared__ float sd[HW];
    __shared__ float bv[256];
    __shared__ int   bi[256];
    for (int idx = tid; idx < 3 * HW; idx += 256) {
        int c = idx >> 10; int j = idx & 1023;
        sf[c][j] = (im[((size_t)b * 3 + c) * HW + j] + 1.0f) * 0.5f;
    }
    __syncthreads();
    float xi = (float)(i & 31) * (1.0f / 31.0f);
    float yi = (float)(i >> 5) * (1.0f / 31.0f);
    float f0i = sf[0][i], f1i = sf[1][i], f2i = sf[2][i];

    for (int cfg = 0; cfg < 2; cfg++) {
        float dw = (cfg == 0) ? 2.0f : 0.1f;
        float xiw = xi * dw, yiw = yi * dw;
        float sqi = f0i*f0i + f1i*f1i + f2i*f2i + xiw*xiw + yiw*yiw;
        for (int j = tid; j < HW; j += 256) {
            float xj = (float)(j & 31) * (1.0f / 31.0f) * dw;
            float yj = (float)(j >> 5) * (1.0f / 31.0f) * dw;
            float f0 = sf[0][j], f1 = sf[1][j], f2 = sf[2][j];
            float sqj = f0*f0 + f1*f1 + f2*f2 + xj*xj + yj*yj;
            float dot = f0i*f0 + f1i*f1 + f2i*f2 + xiw*xj + yiw*yj;
            sd[j] = sqi + sqj - 2.0f * dot;
        }
        __syncthreads();
        if (tid == 0) sd[i] = 3.0e38f;            // exclude diag
        __syncthreads();
        for (int it = 0; it < 10; it++) {
            float best = 3.0e38f; int bidx = HW;
            for (int j = tid; j < HW; j += 256) {
                float v = sd[j];
                if (v < best) { best = v; bidx = j; }
            }
            bv[tid] = best; bi[tid] = bidx;
            __syncthreads();
            for (int s2 = 128; s2 > 0; s2 >>= 1) {
                if (tid < s2) {
                    if (bv[tid+s2] < bv[tid] || (bv[tid+s2] == bv[tid] && bi[tid+s2] < bi[tid])) {
                        bv[tid] = bv[tid+s2]; bi[tid] = bi[tid+s2];
                    }
                }
                __syncthreads();
            }
            if (tid == 0) {
                int js = bi[0];
                g_adj[(size_t)b * HW * HW + (size_t)i  * HW + js] = 1;
                g_adj[(size_t)b * HW * HW + (size_t)js * HW + i ] = 1;
                sd[js] = 3.0e38f;
            }
            __syncthreads();
        }
        __syncthreads();
    }
}

// -------- pixel degrees (1 warp / row) --------
__global__ void pixel_deg_kernel() {
    int g    = blockIdx.x * 8 + (threadIdx.x >> 5);
    int lane = threadIdx.x & 31;
    int b = g >> 10, i = g & 1023;
    const unsigned char* row = g_adj + (size_t)b * HW * HW + (size_t)i * HW;
    float s = 0.f;
    for (int j = lane; j < HW; j += 32) s += (float)row[j];
    #pragma unroll
    for (int o = 16; o > 0; o >>= 1) s += __shfl_xor_sync(0xffffffffu, s, o);
    if (lane == 0) g_deg2[g] = s;
}

__global__ void drs_kernel() {
    int i = blockIdx.x * 256 + threadIdx.x;
    if (i < MM) {
        g_drs[i]  = 1.0f / sqrtf(g_deg[i]);
        g_drs2[i] = 1.0f / sqrtf(g_deg2[i]);
    }
}

// -------- gP += feature-gram @ Psi (sparse scatter, 4 entries/block) --------
__global__ __launch_bounds__(256) void gP_feat_kernel(const float* __restrict__ Psi) {
    int e = blockIdx.x * 4 + (threadIdx.x >> 6);
    int a = threadIdx.x & 63;
    int i = e >> 5; int j = g_topi[e]; float v = g_topv[e];
    float w = 0.5f * v * g_drs[i] * g_drs[j];
    atomicAdd(&g_gP[i * KD + a], w * Psi[(size_t)j * KD + a]);
    atomicAdd(&g_gP[j * KD + a], w * Psi[(size_t)i * KD + a]);
}

// -------- gP += 0.05 * pixel-gram @ Psi (row-owned, no atomics) --------
__global__ void gP_pix_kernel(const float* __restrict__ Psi) {
    int g = blockIdx.x; int b = g >> 10; int a = threadIdx.x;   // 64 threads
    __shared__ unsigned char srow[HW];
    const unsigned char* row = g_adj + (size_t)b * HW * HW + (size_t)(g & 1023) * HW;
    for (int j = a; j < HW / 4; j += 64)
        ((unsigned int*)srow)[j] = ((const unsigned int*)row)[j];
    __syncthreads();
    float wb  = 0.05f * g_drs2[g];
    float acc = 0.f;
    int base  = b * HW;
    for (int j = 0; j < HW; j++) {
        if (srow[j]) acc += wb * g_drs2[base + j] * Psi[(size_t)(base + j) * KD + a];
    }
    g_gP[g * KD + a] += acc;
}

// -------- R0 = Psi^T gP  (64x64) --------
__global__ __launch_bounds__(256) void R_kernel(const float* __restrict__ Psi) {
    __shared__ float sp[KD], sg[KD];
    int tid = threadIdx.x;
    int a = tid >> 2; int b0 = (tid & 3) * 16;
    float acc[16];
    #pragma unroll
    for (int bb = 0; bb < 16; bb++) acc[bb] = 0.f;
    int i0 = blockIdx.x * 128;
    for (int i = i0; i < i0 + 128; i++) {
        if (tid < KD) { sp[tid] = Psi[(size_t)i * KD + tid]; sg[tid] = g_gP[i * KD + tid]; }
        __syncthreads();
        float pa = sp[a];
        #pragma unroll
        for (int bb = 0; bb < 16; bb++) acc[bb] += pa * sg[b0 + bb];
        __syncthreads();
    }
    #pragma unroll
    for (int bb = 0; bb < 16; bb++) atomicAdd(&g_R[a * 64 + b0 + bb], acc[bb]);
}

// -------- scalars: loss = -T*tr/kdim ; reg = T^2 * sum(triu^2,1)/kdim --------
__global__ void final_kernel(float* out, int out_size) {
    __shared__ float str[256], srg[256];
    int tid = threadIdx.x;
    float tr = 0.f, rg = 0.f;
    for (int idx = tid; idx < KD * KD; idx += 256) {
        int a = idx >> 6, bcol = idx & 63;
        float v = g_R[idx];
        if (a == bcol) tr += v;
        else if (bcol > a) { float x = 10.0f * v; rg += x * x; }
    }
    str[tid] = tr; srg[tid] = rg;
    __syncthreads();
    for (int s = 128; s > 0; s >>= 1) {
        if (tid < s) { str[tid] += str[tid + s]; srg[tid] += srg[tid + s]; }
        __syncthreads();
    }
    for (int i = tid; i < out_size; i += 256) out[i] = 0.0f;
    __syncthreads();
    if (tid == 0) {
        if (out_size > 0) out[0] = -10.0f * str[0] / 64.0f;
        if (out_size > 1) out[1] = srg[0] / 64.0f;
    }
}

extern "C" void kernel_launch(void* const* d_in, const int* in_sizes, int n_in,
                              void* d_out, int out_size) {
    const float* hf  = (const float*)d_in[0];   // (8,1024,768)
    const float* Psi = (const float*)d_in[1];   // (8,1024,64)
    const float* im  = (const float*)d_in[2];   // (8,3,32,32)
    float* out = (float*)d_out;

    zero_kernel<<<2048, 256>>>();
    normalize_kernel<<<MM / 8, 256>>>(hf);
    gemm_sym_kernel<<<(64 * 65) / 2, 256>>>();
    topk_kernel<<<MM, 256>>>();
    feat_deg_kernel<<<(MM * KF) / 256, 256>>>();
    pixel_adj_kernel<<<BSZ * HW, 256>>>(im);
    pixel_deg_kernel<<<MM / 8, 256>>>();
    drs_kernel<<<MM / 256, 256>>>();
    gP_feat_kernel<<<(MM * KF) / 4, 256>>>(Psi);
    gP_pix_kernel<<<MM, 64>>>(Psi);
    R_kernel<<<MM / 128, 256>>>(Psi);
    final_kernel<<<1, 256>>>(out, out_size);
}

// round 4
// speedup vs baseline: 1.7484x; 1.7484x over previous
#include <cuda_runtime.h>
#include <math.h>

// Problem constants
#define MM   8192        // bs*n
#define DD   768         // feature dim
#define KD   64          // Psi dim
#define KF   32          // feature top-k
#define HW   1024        // pixels per image
#define BSZ  8           // batch

// -------- device scratch (static, no runtime alloc) --------
__device__ float g_Xn[(size_t)MM*DD];            // normalized features  (25 MB)
__device__ float g_A[(size_t)MM*MM];             // clamped sim matrix   (268 MB)
__device__ float g_topv[MM*KF];
__device__ int   g_topi[MM*KF];
__device__ float g_deg[MM];
__device__ float g_drs[MM];
__device__ unsigned char g_adj[(size_t)BSZ*HW*HW];  // pixel adjacency (8.4 MB)
__device__ float g_deg2[MM];
__device__ float g_drs2[MM];
__device__ float g_gP[MM*KD];                    // gram_total @ Psi (sparse accumulated)
__device__ float g_R[KD*KD];

// -------- zero scratch that accumulates --------
__global__ void zero_kernel() {
    int idx = blockIdx.x * blockDim.x + threadIdx.x;
    int n   = gridDim.x * blockDim.x;
    for (int i = idx; i < MM; i += n) { g_deg[i] = 0.f; g_deg2[i] = 0.f; }
    for (int i = idx; i < MM*KD; i += n) g_gP[i] = 0.f;
    for (int i = idx; i < KD*KD; i += n) g_R[i] = 0.f;
    unsigned int* aj = (unsigned int*)g_adj;
    for (int i = idx; i < (int)((size_t)BSZ*HW*HW/4); i += n) aj[i] = 0u;
}

// -------- row-normalize features (1 warp / row) --------
__global__ void normalize_kernel(const float* __restrict__ hf) {
    int row  = blockIdx.x * 8 + (threadIdx.x >> 5);
    int lane = threadIdx.x & 31;
    const float* x = hf + (size_t)row * DD;
    float s = 0.f;
    for (int k = lane; k < DD; k += 32) { float v = x[k]; s += v * v; }
    #pragma unroll
    for (int o = 16; o > 0; o >>= 1) s += __shfl_xor_sync(0xffffffffu, s, o);
    float inv = 1.0f / sqrtf(s);
    float* y = g_Xn + (size_t)row * DD;
    for (int k = lane; k < DD; k += 32) y[k] = x[k] * inv;
}

// -------- symmetric SGEMM: A = clamp(Xn Xn^T), upper-tri tiles only --------
__global__ __launch_bounds__(256) void gemm_sym_kernel() {
    int t  = blockIdx.x;
    int bc = (int)((sqrtf(8.0f * (float)t + 1.0f) - 1.0f) * 0.5f);
    while ((bc + 1) * (bc + 2) / 2 <= t) bc++;
    while (bc * (bc + 1) / 2 > t) bc--;
    int br = t - bc * (bc + 1) / 2;          // br <= bc

    __shared__ float As[16][132];
    __shared__ float Bs[16][132];

    int tid = threadIdx.x;
    int r   = tid >> 2, kq = tid & 3;        // loader mapping
    int tx  = tid & 15, ty = tid >> 4;       // compute mapping (16x16 threads, 8x8 each)

    const float* Abase = g_Xn + (size_t)(br * 128) * DD;
    const float* Bbase = g_Xn + (size_t)(bc * 128) * DD;

    float acc[8][8];
    #pragma unroll
    for (int m = 0; m < 8; m++)
        #pragma unroll
        for (int n = 0; n < 8; n++) acc[m][n] = 0.f;

    for (int k0 = 0; k0 < DD; k0 += 16) {
        float4 a0 = *(const float4*)(Abase + (size_t)r        * DD + k0 + kq * 4);
        float4 a1 = *(const float4*)(Abase + (size_t)(r + 64) * DD + k0 + kq * 4);
        float4 b0 = *(const float4*)(Bbase + (size_t)r        * DD + k0 + kq * 4);
        float4 b1 = *(const float4*)(Bbase + (size_t)(r + 64) * DD + k0 + kq * 4);
        __syncthreads();
        As[kq*4+0][r] = a0.x; As[kq*4+1][r] = a0.y; As[kq*4+2][r] = a0.z; As[kq*4+3][r] = a0.w;
        As[kq*4+0][r+64] = a1.x; As[kq*4+1][r+64] = a1.y; As[kq*4+2][r+64] = a1.z; As[kq*4+3][r+64] = a1.w;
        Bs[kq*4+0][r] = b0.x; Bs[kq*4+1][r] = b0.y; Bs[kq*4+2][r] = b0.z; Bs[kq*4+3][r] = b0.w;
        Bs[kq*4+0][r+64] = b1.x; Bs[kq*4+1][r+64] = b1.y; Bs[kq*4+2][r+64] = b1.z; Bs[kq*4+3][r+64] = b1.w;
        __syncthreads();
        #pragma unroll
        for (int kk = 0; kk < 16; kk++) {
            float a[8], b[8];
            *(float4*)&a[0] = *(const float4*)&As[kk][ty * 8];
            *(float4*)&a[4] = *(const float4*)&As[kk][ty * 8 + 4];
            *(float4*)&b[0] = *(const float4*)&Bs[kk][tx * 8];
            *(float4*)&b[4] = *(const float4*)&Bs[kk][tx * 8 + 4];
            #pragma unroll
            for (int m = 0; m < 8; m++)
                #pragma unroll
                for (int n = 0; n < 8; n++) acc[m][n] += a[m] * b[n];
        }
    }

    #pragma unroll
    for (int m = 0; m < 8; m++) {
        int i = br * 128 + ty * 8 + m;
        #pragma unroll
        for (int n = 0; n < 8; n++) {
            int j = bc * 128 + tx * 8 + n;
            float v = acc[m][n];
            v = (i == j) ? 0.0f : fmaxf(v, 0.0f);   // diag=-inf then clamp -> 0
            g_A[(size_t)i * MM + j] = v;
            g_A[(size_t)j * MM + i] = v;            // symmetric fill
        }
    }
}

// -------- per-row top-32: shared row + register top-2 cache --------
// Thread t owns j = t + 256*i. Invariant: each iteration's global winner is the
// owner thread's cached local #1, so the owner just promotes its cached #2.
// Full 32-element rescan only when a thread's cache is exhausted (rare).
__global__ __launch_bounds__(256) void topk_kernel() {
    int row = blockIdx.x;
    __shared__ float s[MM];       // 32 KB row copy (for rescans + removal marks)
    __shared__ float wv[8];
    __shared__ int   wi[8];
    __shared__ int   sbi_s;
    int tid = threadIdx.x;
    const float* arow = g_A + (size_t)row * MM;

    // initial load + local top-2 (strict > and ascending order => lowest index on ties)
    float v1 = -1.0f, v2 = -1.0f; int i1 = MM, i2 = MM;
    #pragma unroll 8
    for (int i = 0; i < 32; i++) {
        int j = tid + (i << 8);
        float v = arow[j];
        s[j] = v;
        if (v > v1)      { v2 = v1; i2 = i1; v1 = v; i1 = j; }
        else if (v > v2) { v2 = v;  i2 = j; }
    }
    int cnt = 2;
    __syncthreads();

    for (int it = 0; it < KF; it++) {
        // warp-level reduce of (v1, i1)
        float v = v1; int idx = i1;
        #pragma unroll
        for (int o = 16; o > 0; o >>= 1) {
            float ov = __shfl_xor_sync(0xffffffffu, v, o);
            int   oi = __shfl_xor_sync(0xffffffffu, idx, o);
            if (ov > v || (ov == v && oi < idx)) { v = ov; idx = oi; }
        }
        if ((tid & 31) == 0) { wv[tid >> 5] = v; wi[tid >> 5] = idx; }
        __syncthreads();
        if (tid < 8) {
            float v8 = wv[tid]; int i8 = wi[tid];
            #pragma unroll
            for (int o = 4; o > 0; o >>= 1) {
                float ov = __shfl_xor_sync(0x000000ffu, v8, o);
                int   oi = __shfl_xor_sync(0x000000ffu, i8, o);
                if (ov > v8 || (ov == v8 && oi < i8)) { v8 = ov; i8 = oi; }
            }
            if (tid == 0) {
                g_topv[row * KF + it] = v8;
                g_topi[row * KF + it] = i8;
                sbi_s = i8;
            }
        }
        __syncthreads();
        int win = sbi_s;
        if ((win & 255) == tid) {
            s[win] = -1.0f;                 // mark removed (values are >= 0)
            if (cnt == 2) {                 // promote cached #2
                v1 = v2; i1 = i2; cnt = 1;
            } else {                        // rare: full rescan of owned 32
                v1 = -1.0f; i1 = MM; v2 = -1.0f; i2 = MM;
                #pragma unroll 8
                for (int i = 0; i < 32; i++) {
                    int j = tid + (i << 8);
                    float vv = s[j];
                    if (vv > v1)      { v2 = v1; i2 = i1; v1 = vv; i1 = j; }
                    else if (vv > v2) { v2 = vv; i2 = j; }
                }
                cnt = 2;
            }
        }
        // no barrier needed here: next iteration's reduce reads only registers,
        // and the wv/wi rewrite is fenced by the barrier after the warp stage.
    }
}

// -------- feature degrees: deg = rowsum((res+res^T)/2) --------
__global__ void feat_deg_kernel() {
    int e = blockIdx.x * blockDim.x + threadIdx.x;
    if (e >= MM * KF) return;
    int i = e >> 5; int j = g_topi[e]; float v = g_topv[e];
    atomicAdd(&g_deg[i], 0.5f * v);
    atomicAdd(&g_deg[j], 0.5f * v);
}

// -------- pixel adjacency: per (batch,row) top-10 for both (k,dw) configs --------
__global__ __launch_bounds__(256) void pixel_adj_kernel(const float* __restrict__ im) {
    int blk = blockIdx.x; int b = blk >> 10; int i = blk & 1023;
    int tid = threadIdx.x;
    __shared__ float sf[3][HW];
    __shared__ float sd[HW];
    __shared__ float bv[256];
    __shared__ int   bi[256];
    for (int idx = tid; idx < 3 * HW; idx += 256) {
        int c = idx >> 10; int j = idx & 1023;
        sf[c][j] = (im[((size_t)b * 3 + c) * HW + j] + 1.0f) * 0.5f;
    }
    __syncthreads();
    float xi = (float)(i & 31) * (1.0f / 31.0f);
    float yi = (float)(i >> 5) * (1.0f / 31.0f);
    float f0i = sf[0][i], f1i = sf[1][i], f2i = sf[2][i];

    for (int cfg = 0; cfg < 2; cfg++) {
        float dw = (cfg == 0) ? 2.0f : 0.1f;
        float xiw = xi * dw, yiw = yi * dw;
        float sqi = f0i*f0i + f1i*f1i + f2i*f2i + xiw*xiw + yiw*yiw;
        for (int j = tid; j < HW; j += 256) {
            float xj = (float)(j & 31) * (1.0f / 31.0f) * dw;
            float yj = (float)(j >> 5) * (1.0f / 31.0f) * dw;
            float f0 = sf[0][j], f1 = sf[1][j], f2 = sf[2][j];
            float sqj = f0*f0 + f1*f1 + f2*f2 + xj*xj + yj*yj;
            float dot = f0i*f0 + f1i*f1 + f2i*f2 + xiw*xj + yiw*yj;
            sd[j] = sqi + sqj - 2.0f * dot;
        }
        __syncthreads();
        if (tid == 0) sd[i] = 3.0e38f;            // exclude diag
        __syncthreads();
        for (int it = 0; it < 10; it++) {
            float best = 3.0e38f; int bidx = HW;
            for (int j = tid; j < HW; j += 256) {
                float v = sd[j];
                if (v < best) { best = v; bidx = j; }
            }
            bv[tid] = best; bi[tid] = bidx;
            __syncthreads();
            for (int s2 = 128; s2 > 0; s2 >>= 1) {
                if (tid < s2) {
                    if (bv[tid+s2] < bv[tid] || (bv[tid+s2] == bv[tid] && bi[tid+s2] < bi[tid])) {
                        bv[tid] = bv[tid+s2]; bi[tid] = bi[tid+s2];
                    }
                }
                __syncthreads();
            }
            if (tid == 0) {
                int js = bi[0];
                g_adj[(size_t)b * HW * HW + (size_t)i  * HW + js] = 1;
                g_adj[(size_t)b * HW * HW + (size_t)js * HW + i ] = 1;
                sd[js] = 3.0e38f;
            }
            __syncthreads();
        }
        __syncthreads();
    }
}

// -------- pixel degrees (1 warp / row) --------
__global__ void pixel_deg_kernel() {
    int g    = blockIdx.x * 8 + (threadIdx.x >> 5);
    int lane = threadIdx.x & 31;
    int b = g >> 10, i = g & 1023;
    const unsigned char* row = g_adj + (size_t)b * HW * HW + (size_t)i * HW;
    float s = 0.f;
    for (int j = lane; j < HW; j += 32) s += (float)row[j];
    #pragma unroll
    for (int o = 16; o > 0; o >>= 1) s += __shfl_xor_sync(0xffffffffu, s, o);
    if (lane == 0) g_deg2[g] = s;
}

__global__ void drs_kernel() {
    int i = blockIdx.x * 256 + threadIdx.x;
    if (i < MM) {
        g_drs[i]  = 1.0f / sqrtf(g_deg[i]);
        g_drs2[i] = 1.0f / sqrtf(g_deg2[i]);
    }
}

// -------- gP += feature-gram @ Psi (sparse scatter, 4 entries/block) --------
__global__ __launch_bounds__(256) void gP_feat_kernel(const float* __restrict__ Psi) {
    int e = blockIdx.x * 4 + (threadIdx.x >> 6);
    int a = threadIdx.x & 63;
    int i = e >> 5; int j = g_topi[e]; float v = g_topv[e];
    float w = 0.5f * v * g_drs[i] * g_drs[j];
    atomicAdd(&g_gP[i * KD + a], w * Psi[(size_t)j * KD + a]);
    atomicAdd(&g_gP[j * KD + a], w * Psi[(size_t)i * KD + a]);
}

// -------- gP += 0.05 * pixel-gram @ Psi (row-owned, no atomics) --------
__global__ void gP_pix_kernel(const float* __restrict__ Psi) {
    int g = blockIdx.x; int b = g >> 10; int a = threadIdx.x;   // 64 threads
    __shared__ unsigned char srow[HW];
    const unsigned char* row = g_adj + (size_t)b * HW * HW + (size_t)(g & 1023) * HW;
    for (int j = a; j < HW / 4; j += 64)
        ((unsigned int*)srow)[j] = ((const unsigned int*)row)[j];
    __syncthreads();
    float wb  = 0.05f * g_drs2[g];
    float acc = 0.f;
    int base  = b * HW;
    for (int j = 0; j < HW; j++) {
        if (srow[j]) acc += wb * g_drs2[base + j] * Psi[(size_t)(base + j) * KD + a];
    }
    g_gP[g * KD + a] += acc;
}

// -------- R0 = Psi^T gP  (64x64) --------
__global__ __launch_bounds__(256) void R_kernel(const float* __restrict__ Psi) {
    __shared__ float sp[KD], sg[KD];
    int tid = threadIdx.x;
    int a = tid >> 2; int b0 = (tid & 3) * 16;
    float acc[16];
    #pragma unroll
    for (int bb = 0; bb < 16; bb++) acc[bb] = 0.f;
    int i0 = blockIdx.x * 128;
    for (int i = i0; i < i0 + 128; i++) {
        if (tid < KD) { sp[tid] = Psi[(size_t)i * KD + tid]; sg[tid] = g_gP[i * KD + tid]; }
        __syncthreads();
        float pa = sp[a];
        #pragma unroll
        for (int bb = 0; bb < 16; bb++) acc[bb] += pa * sg[b0 + bb];
        __syncthreads();
    }
    #pragma unroll
    for (int bb = 0; bb < 16; bb++) atomicAdd(&g_R[a * 64 + b0 + bb], acc[bb]);
}

// -------- scalars: loss = -T*tr/kdim ; reg = T^2 * sum(triu^2,1)/kdim --------
__global__ void final_kernel(float* out, int out_size) {
    __shared__ float str[256], srg[256];
    int tid = threadIdx.x;
    float tr = 0.f, rg = 0.f;
    for (int idx = tid; idx < KD * KD; idx += 256) {
        int a = idx >> 6, bcol = idx & 63;
        float v = g_R[idx];
        if (a == bcol) tr += v;
        else if (bcol > a) { float x = 10.0f * v; rg += x * x; }
    }
    str[tid] = tr; srg[tid] = rg;
    __syncthreads();
    for (int s = 128; s > 0; s >>= 1) {
        if (tid < s) { str[tid] += str[tid + s]; srg[tid] += srg[tid + s]; }
        __syncthreads();
    }
    for (int i = tid; i < out_size; i += 256) out[i] = 0.0f;
    __syncthreads();
    if (tid == 0) {
        if (out_size > 0) out[0] = -10.0f * str[0] / 64.0f;
        if (out_size > 1) out[1] = srg[0] / 64.0f;
    }
}

extern "C" void kernel_launch(void* const* d_in, const int* in_sizes, int n_in,
                              void* d_out, int out_size) {
    const float* hf  = (const float*)d_in[0];   // (8,1024,768)
    const float* Psi = (const float*)d_in[1];   // (8,1024,64)
    const float* im  = (const float*)d_in[2];   // (8,3,32,32)
    float* out = (float*)d_out;

    zero_kernel<<<2048, 256>>>();
    normalize_kernel<<<MM / 8, 256>>>(hf);
    gemm_sym_kernel<<<(64 * 65) / 2, 256>>>();
    topk_kernel<<<MM, 256>>>();
    feat_deg_kernel<<<(MM * KF) / 256, 256>>>();
    pixel_adj_kernel<<<BSZ * HW, 256>>>(im);
    pixel_deg_kernel<<<MM / 8, 256>>>();
    drs_kernel<<<MM / 256, 256>>>();
    gP_feat_kernel<<<(MM * KF) / 4, 256>>>(Psi);
    gP_pix_kernel<<<MM, 64>>>(Psi);
    R_kernel<<<MM / 128, 256>>>(Psi);
    final_kernel<<<1, 256>>>(out, out_size);
}

// round 9
// speedup vs baseline: 2.7751x; 1.5872x over previous
#include <cuda_runtime.h>
#include <cuda_bf16.h>
#include <math.h>
#include <stdint.h>

// Problem constants
#define MM   8192        // bs*n
#define DD   768         // feature dim
#define KD   64          // Psi dim
#define KF   32          // feature top-k
#define HW   1024        // pixels per image
#define BSZ  8           // batch

// GEMM tiling (mma.sync bf16 path, family-portable)
#define TB      128                    // output tile 128x128
#define NTILE   (MM/TB)                // 64
#define NPAIRS  (NTILE*(NTILE+1)/2)    // 2080
#define KCH     64                     // K elems per chunk
#define NCHUNK  (DD/KCH)               // 12
#define LDW     72                     // smem row stride in bf16 (64 + 8 pad)
#define TILEB   (128*LDW*2)            // 18432 B per operand tile
#define STAGEB  (4*TILEB)              // 73728 B per stage (Ahi,Alo,Bhi,Blo)
#define SM_TOTAL (2*STAGEB)            // 147456 B dynamic smem

// -------- device scratch (static, no runtime alloc) --------
__device__ __nv_bfloat16 g_Xhi[(size_t)MM*DD];   // 12.6 MB
__device__ __nv_bfloat16 g_Xlo[(size_t)MM*DD];   // 12.6 MB
__device__ float g_A[(size_t)MM*MM];             // clamped sim matrix (268 MB)
__device__ float g_topv[MM*KF];
__device__ int   g_topi[MM*KF];
__device__ float g_deg[MM];
__device__ float g_drs[MM];
__device__ unsigned char g_adj[(size_t)BSZ*HW*HW];
__device__ float g_deg2[MM];
__device__ float g_drs2[MM];
__device__ float g_gP[MM*KD];
__device__ float g_R[KD*KD];

// ================= helpers =================
__device__ __forceinline__ uint32_t smem_u32(const void* p) {
    uint32_t a;
    asm("{ .reg .u64 t; cvta.to.shared.u64 t, %1; cvt.u32.u64 %0, t; }" : "=r"(a) : "l"(p));
    return a;
}
__device__ __forceinline__ void ldm4(uint32_t* r, uint32_t addr) {
    asm volatile("ldmatrix.sync.aligned.m8n8.x4.shared.b16 {%0,%1,%2,%3}, [%4];"
        : "=r"(r[0]), "=r"(r[1]), "=r"(r[2]), "=r"(r[3]) : "r"(addr));
}
__device__ __forceinline__ void mma_bf16(float* d, const uint32_t* a, uint32_t b0, uint32_t b1) {
    asm volatile("mma.sync.aligned.m16n8k16.row.col.f32.bf16.bf16.f32 "
        "{%0,%1,%2,%3}, {%4,%5,%6,%7}, {%8,%9}, {%0,%1,%2,%3};"
        : "+f"(d[0]), "+f"(d[1]), "+f"(d[2]), "+f"(d[3])
        : "r"(a[0]), "r"(a[1]), "r"(a[2]), "r"(a[3]), "r"(b0), "r"(b1));
}
__device__ __forceinline__ void cpasync16(uint32_t dst, const void* src) {
    asm volatile("cp.async.cg.shared.global [%0], [%1], 16;" :: "r"(dst), "l"(src));
}
#define CP_COMMIT() asm volatile("cp.async.commit_group;" ::: "memory")
#define CP_WAIT1()  asm volatile("cp.async.wait_group 1;" ::: "memory")
#define CP_WAIT0()  asm volatile("cp.async.wait_group 0;" ::: "memory")

// -------- zero scratch that accumulates --------
__global__ void zero_kernel() {
    int idx = blockIdx.x * blockDim.x + threadIdx.x;
    int n   = gridDim.x * blockDim.x;
    for (int i = idx; i < MM; i += n) { g_deg[i] = 0.f; g_deg2[i] = 0.f; }
    for (int i = idx; i < MM*KD; i += n) g_gP[i] = 0.f;
    for (int i = idx; i < KD*KD; i += n) g_R[i] = 0.f;
    unsigned int* aj = (unsigned int*)g_adj;
    for (int i = idx; i < (int)((size_t)BSZ*HW*HW/4); i += n) aj[i] = 0u;
}

// -------- normalize + bf16 split (1 warp / row) --------
__global__ void split_kernel(const float* __restrict__ hf) {
    int row  = blockIdx.x * 8 + (threadIdx.x >> 5);
    int lane = threadIdx.x & 31;
    const float* x = hf + (size_t)row * DD;
    float s = 0.f;
    for (int k = lane; k < DD; k += 32) { float v = x[k]; s += v * v; }
    #pragma unroll
    for (int o = 16; o > 0; o >>= 1) s += __shfl_xor_sync(0xffffffffu, s, o);
    float inv = 1.0f / sqrtf(s);
    for (int k = lane; k < DD; k += 32) {
        float v = x[k] * inv;
        __nv_bfloat16 hi = __float2bfloat16(v);
        __nv_bfloat16 lo = __float2bfloat16(v - __bfloat162float(hi));
        g_Xhi[(size_t)row * DD + k] = hi;
        g_Xlo[(size_t)row * DD + k] = lo;
    }
}

// -------- bf16-split symmetric GEMM via mma.sync (HMMA) --------
__global__ __launch_bounds__(256) void gemm_mma_kernel() {
    extern __shared__ char sm[];
    uint32_t sb = smem_u32(sm);
    int tid  = threadIdx.x;
    int wid  = tid >> 5;
    int lane = tid & 31;
    int wm   = wid & 3;          // M quadrant (32 rows each)
    int wn   = wid >> 2;         // N half (64 cols each)

    // triangular tile decode (br <= bc)
    int t  = blockIdx.x;
    int bc = (int)((sqrtf(8.0f * (float)t + 1.0f) - 1.0f) * 0.5f);
    while ((bc + 1) * (bc + 2) / 2 <= t) bc++;
    while (bc * (bc + 1) / 2 > t) bc--;
    int br = t - bc * (bc + 1) / 2;

    const char* srcs[4] = {
        (const char*)g_Xhi + (size_t)(br * TB) * (DD * 2),
        (const char*)g_Xlo + (size_t)(br * TB) * (DD * 2),
        (const char*)g_Xhi + (size_t)(bc * TB) * (DD * 2),
        (const char*)g_Xlo + (size_t)(bc * TB) * (DD * 2)
    };

    float acc[2][8][4];
    #pragma unroll
    for (int mt = 0; mt < 2; mt++)
        #pragma unroll
        for (int nt = 0; nt < 8; nt++)
            #pragma unroll
            for (int q = 0; q < 4; q++) acc[mt][nt][q] = 0.f;

    // ldmatrix per-lane addressing: row = lane&15, k-half = lane>>4
    uint32_t rowsel = (uint32_t)(lane & 15);
    uint32_t kbyte  = (uint32_t)((lane >> 4) * 16);   // 8 bf16 = 16 B

    // ---- prologue: load chunk 0 into stage 0 ----
    {
        uint32_t dstb = sb;
        #pragma unroll
        for (int tt = 0; tt < 4; tt++) {
            #pragma unroll
            for (int i = 0; i < 4; i++) {
                int idx = i * 256 + tid;
                int r = idx >> 3, seg = idx & 7;
                cpasync16(dstb + tt * TILEB + r * (LDW * 2) + seg * 16,
                          srcs[tt] + (size_t)r * (DD * 2) + seg * 16);
            }
        }
        CP_COMMIT();
    }

    for (int c = 0; c < NCHUNK; c++) {
        if (c + 1 < NCHUNK) {
            uint32_t dstb = sb + ((c + 1) & 1) * STAGEB;
            int koff = (c + 1) * (KCH * 2);
            #pragma unroll
            for (int tt = 0; tt < 4; tt++) {
                #pragma unroll
                for (int i = 0; i < 4; i++) {
                    int idx = i * 256 + tid;
                    int r = idx >> 3, seg = idx & 7;
                    cpasync16(dstb + tt * TILEB + r * (LDW * 2) + seg * 16,
                              srcs[tt] + (size_t)r * (DD * 2) + koff + seg * 16);
                }
            }
            CP_COMMIT();
            CP_WAIT1();
        } else {
            CP_WAIT0();
        }
        __syncthreads();

        uint32_t stb = sb + (c & 1) * STAGEB;
        uint32_t aHb = stb + 0 * TILEB + (wm * 32 + rowsel) * (LDW * 2) + kbyte;
        uint32_t aLb = stb + 1 * TILEB + (wm * 32 + rowsel) * (LDW * 2) + kbyte;
        uint32_t bHb = stb + 2 * TILEB + (wn * 64 + rowsel) * (LDW * 2) + kbyte;
        uint32_t bLb = stb + 3 * TILEB + (wn * 64 + rowsel) * (LDW * 2) + kbyte;

        #pragma unroll
        for (int ks = 0; ks < 4; ks++) {
            uint32_t kb = ks * 32;     // 16 bf16 per k-step
            uint32_t aH[2][4], aL[2][4], bH[4][4], bL[4][4];
            #pragma unroll
            for (int mt = 0; mt < 2; mt++) {
                ldm4(aH[mt], aHb + mt * (16 * LDW * 2) + kb);
                ldm4(aL[mt], aLb + mt * (16 * LDW * 2) + kb);
            }
            #pragma unroll
            for (int np = 0; np < 4; np++) {
                ldm4(bH[np], bHb + np * (16 * LDW * 2) + kb);
                ldm4(bL[np], bLb + np * (16 * LDW * 2) + kb);
            }
            #pragma unroll
            for (int mt = 0; mt < 2; mt++) {
                #pragma unroll
                for (int nt = 0; nt < 8; nt++) {
                    int np = nt >> 1, od = nt & 1;
                    mma_bf16(acc[mt][nt], aH[mt], bH[np][od], bH[np][od + 2]);
                    mma_bf16(acc[mt][nt], aH[mt], bL[np][od], bL[np][od + 2]);
                    mma_bf16(acc[mt][nt], aL[mt], bH[np][od], bH[np][od + 2]);
                }
            }
        }
        __syncthreads();
    }

    // ---- epilogue: stage tile in smem, clamp+diag, coalesced direct+mirror ----
    float* ep = (float*)sm;            // [128][129] = 66048 B, fits in stage mem
    #pragma unroll
    for (int mt = 0; mt < 2; mt++) {
        #pragma unroll
        for (int nt = 0; nt < 8; nt++) {
            int r0 = wm * 32 + mt * 16 + (lane >> 2);
            int c0 = wn * 64 + nt * 8 + (lane & 3) * 2;
            ep[r0 * 129 + c0]           = acc[mt][nt][0];
            ep[r0 * 129 + c0 + 1]       = acc[mt][nt][1];
            ep[(r0 + 8) * 129 + c0]     = acc[mt][nt][2];
            ep[(r0 + 8) * 129 + c0 + 1] = acc[mt][nt][3];
        }
    }
    __syncthreads();

    // direct rows (coalesced)
    #pragma unroll
    for (int i = 0; i < 64; i++) {
        int idx = i * 256 + tid;
        int r = idx >> 7, cc = idx & 127;
        int ig = br * TB + r, jg = bc * TB + cc;
        float v = ep[r * 129 + cc];
        v = (ig == jg) ? 0.0f : fmaxf(v, 0.0f);
        g_A[(size_t)ig * MM + jg] = v;
    }
    // mirror rows (transposed read from smem, coalesced write)
    if (br != bc) {
        #pragma unroll
        for (int i = 0; i < 64; i++) {
            int idx = i * 256 + tid;
            int cc = idx >> 7, r = idx & 127;
            float v = ep[r * 129 + cc];
            v = fmaxf(v, 0.0f);
            g_A[(size_t)(bc * TB + cc) * MM + br * TB + r] = v;
        }
    }
}

// -------- per-row top-32: shared row + register top-2 cache --------
__global__ __launch_bounds__(256) void topk_kernel() {
    int row = blockIdx.x;
    __shared__ float s[MM];
    __shared__ float wv[8];
    __shared__ int   wi[8];
    __shared__ int   sbi_s;
    int tid = threadIdx.x;
    const float* arow = g_A + (size_t)row * MM;

    float v1 = -1.0f, v2 = -1.0f; int i1 = MM, i2 = MM;
    #pragma unroll 8
    for (int i = 0; i < 32; i++) {
        int j = tid + (i << 8);
        float v = arow[j];
        s[j] = v;
        if (v > v1)      { v2 = v1; i2 = i1; v1 = v; i1 = j; }
        else if (v > v2) { v2 = v;  i2 = j; }
    }
    int cnt = 2;
    __syncthreads();

    for (int it = 0; it < KF; it++) {
        float v = v1; int idx = i1;
        #pragma unroll
        for (int o = 16; o > 0; o >>= 1) {
            float ov = __shfl_xor_sync(0xffffffffu, v, o);
            int   oi = __shfl_xor_sync(0xffffffffu, idx, o);
            if (ov > v || (ov == v && oi < idx)) { v = ov; idx = oi; }
        }
        if ((tid & 31) == 0) { wv[tid >> 5] = v; wi[tid >> 5] = idx; }
        __syncthreads();
        if (tid < 8) {
            float v8 = wv[tid]; int i8 = wi[tid];
            #pragma unroll
            for (int o = 4; o > 0; o >>= 1) {
                float ov = __shfl_xor_sync(0x000000ffu, v8, o);
                int   oi = __shfl_xor_sync(0x000000ffu, i8, o);
                if (ov > v8 || (ov == v8 && oi < i8)) { v8 = ov; i8 = oi; }
            }
            if (tid == 0) {
                g_topv[row * KF + it] = v8;
                g_topi[row * KF + it] = i8;
                sbi_s = i8;
            }
        }
        __syncthreads();
        int win = sbi_s;
        if ((win & 255) == tid) {
            s[win] = -1.0f;
            if (cnt == 2) {
                v1 = v2; i1 = i2; cnt = 1;
            } else {
                v1 = -1.0f; i1 = MM; v2 = -1.0f; i2 = MM;
                #pragma unroll 8
                for (int i = 0; i < 32; i++) {
                    int j = tid + (i << 8);
                    float vv = s[j];
                    if (vv > v1)      { v2 = v1; i2 = i1; v1 = vv; i1 = j; }
                    else if (vv > v2) { v2 = vv; i2 = j; }
                }
                cnt = 2;
            }
        }
    }
}

// -------- feature degrees --------
__global__ void feat_deg_kernel() {
    int e = blockIdx.x * blockDim.x + threadIdx.x;
    if (e >= MM * KF) return;
    int i = e >> 5; int j = g_topi[e]; float v = g_topv[e];
    atomicAdd(&g_deg[i], 0.5f * v);
    atomicAdd(&g_deg[j], 0.5f * v);
}

// -------- pixel adjacency --------
__global__ __launch_bounds__(256) void pixel_adj_kernel(const float* __restrict__ im) {
    int blk = blockIdx.x; int b = blk >> 10; int i = blk & 1023;
    int tid = threadIdx.x;
    __shared__ float sf[3][HW];
    __shared__ float sd[HW];
    __shared__ float bv[256];
    __shared__ int   bi[256];
    for (int idx = tid; idx < 3 * HW; idx += 256) {
        int c = idx >> 10; int j = idx & 1023;
        sf[c][j] = (im[((size_t)b * 3 + c) * HW + j] + 1.0f) * 0.5f;
    }
    __syncthreads();
    float xi = (float)(i & 31) * (1.0f / 31.0f);
    float yi = (float)(i >> 5) * (1.0f / 31.0f);
    float f0i = sf[0][i], f1i = sf[1][i], f2i = sf[2][i];

    for (int cfg = 0; cfg < 2; cfg++) {
        float dw = (cfg == 0) ? 2.0f : 0.1f;
        float xiw = xi * dw, yiw = yi * dw;
        float sqi = f0i*f0i + f1i*f1i + f2i*f2i + xiw*xiw + yiw*yiw;
        for (int j = tid; j < HW; j += 256) {
            float xj = (float)(j & 31) * (1.0f / 31.0f) * dw;
            float yj = (float)(j >> 5) * (1.0f / 31.0f) * dw;
            float f0 = sf[0][j], f1 = sf[1][j], f2 = sf[2][j];
            float sqj = f0*f0 + f1*f1 + f2*f2 + xj*xj + yj*yj;
            float dot = f0i*f0 + f1i*f1 + f2i*f2 + xiw*xj + yiw*yj;
            sd[j] = sqi + sqj - 2.0f * dot;
        }
        __syncthreads();
        if (tid == 0) sd[i] = 3.0e38f;
        __syncthreads();
        for (int it = 0; it < 10; it++) {
            float best = 3.0e38f; int bidx = HW;
            for (int j = tid; j < HW; j += 256) {
                float v = sd[j];
                if (v < best) { best = v; bidx = j; }
            }
            bv[tid] = best; bi[tid] = bidx;
            __syncthreads();
            for (int s2 = 128; s2 > 0; s2 >>= 1) {
                if (tid < s2) {
                    if (bv[tid+s2] < bv[tid] || (bv[tid+s2] == bv[tid] && bi[tid+s2] < bi[tid])) {
                        bv[tid] = bv[tid+s2]; bi[tid] = bi[tid+s2];
                    }
                }
                __syncthreads();
            }
            if (tid == 0) {
                int js = bi[0];
                g_adj[(size_t)b * HW * HW + (size_t)i  * HW + js] = 1;
                g_adj[(size_t)b * HW * HW + (size_t)js * HW + i ] = 1;
                sd[js] = 3.0e38f;
            }
            __syncthreads();
        }
        __syncthreads();
    }
}

// -------- pixel degrees --------
__global__ void pixel_deg_kernel() {
    int g    = blockIdx.x * 8 + (threadIdx.x >> 5);
    int lane = threadIdx.x & 31;
    int b = g >> 10, i = g & 1023;
    const unsigned char* row = g_adj + (size_t)b * HW * HW + (size_t)i * HW;
    float s = 0.f;
    for (int j = lane; j < HW; j += 32) s += (float)row[j];
    #pragma unroll
    for (int o = 16; o > 0; o >>= 1) s += __shfl_xor_sync(0xffffffffu, s, o);
    if (lane == 0) g_deg2[g] = s;
}

__global__ void drs_kernel() {
    int i = blockIdx.x * 256 + threadIdx.x;
    if (i < MM) {
        g_drs[i]  = 1.0f / sqrtf(g_deg[i]);
        g_drs2[i] = 1.0f / sqrtf(g_deg2[i]);
    }
}

// -------- gP += feature-gram @ Psi --------
__global__ __launch_bounds__(256) void gP_feat_kernel(const float* __restrict__ Psi) {
    int e = blockIdx.x * 4 + (threadIdx.x >> 6);
    int a = threadIdx.x & 63;
    int i = e >> 5; int j = g_topi[e]; float v = g_topv[e];
    float w = 0.5f * v * g_drs[i] * g_drs[j];
    atomicAdd(&g_gP[i * KD + a], w * Psi[(size_t)j * KD + a]);
    atomicAdd(&g_gP[j * KD + a], w * Psi[(size_t)i * KD + a]);
}

// -------- gP += 0.05 * pixel-gram @ Psi --------
__global__ void gP_pix_kernel(const float* __restrict__ Psi) {
    int g = blockIdx.x; int b = g >> 10; int a = threadIdx.x;
    __shared__ unsigned char srow[HW];
    const unsigned char* row = g_adj + (size_t)b * HW * HW + (size_t)(g & 1023) * HW;
    for (int j = a; j < HW / 4; j += 64)
        ((unsigned int*)srow)[j] = ((const unsigned int*)row)[j];
    __syncthreads();
    float wb  = 0.05f * g_drs2[g];
    float acc = 0.f;
    int base  = b * HW;
    for (int j = 0; j < HW; j++) {
        if (srow[j]) acc += wb * g_drs2[base + j] * Psi[(size_t)(base + j) * KD + a];
    }
    g_gP[g * KD + a] += acc;
}

// -------- R = Psi^T gP --------
__global__ __launch_bounds__(256) void R_kernel(const float* __restrict__ Psi) {
    __shared__ float sp[KD], sg[KD];
    int tid = threadIdx.x;
    int a = tid >> 2; int b0 = (tid & 3) * 16;
    float acc[16];
    #pragma unroll
    for (int bb = 0; bb < 16; bb++) acc[bb] = 0.f;
    int i0 = blockIdx.x * 128;
    for (int i = i0; i < i0 + 128; i++) {
        if (tid < KD) { sp[tid] = Psi[(size_t)i * KD + tid]; sg[tid] = g_gP[i * KD + tid]; }
        __syncthreads();
        float pa = sp[a];
        #pragma unroll
        for (int bb = 0; bb < 16; bb++) acc[bb] += pa * sg[b0 + bb];
        __syncthreads();
    }
    #pragma unroll
    for (int bb = 0; bb < 16; bb++) atomicAdd(&g_R[a * 64 + b0 + bb], acc[bb]);
}

// -------- final scalars --------
__global__ void final_kernel(float* out, int out_size) {
    __shared__ float str[256], srg[256];
    int tid = threadIdx.x;
    float tr = 0.f, rg = 0.f;
    for (int idx = tid; idx < KD * KD; idx += 256) {
        int a = idx >> 6, bcol = idx & 63;
        float v = g_R[idx];
        if (a == bcol) tr += v;
        else if (bcol > a) { float x = 10.0f * v; rg += x * x; }
    }
    str[tid] = tr; srg[tid] = rg;
    __syncthreads();
    for (int s = 128; s > 0; s >>= 1) {
        if (tid < s) { str[tid] += str[tid + s]; srg[tid] += srg[tid + s]; }
        __syncthreads();
    }
    for (int i = tid; i < out_size; i += 256) out[i] = 0.0f;
    __syncthreads();
    if (tid == 0) {
        if (out_size > 0) out[0] = -10.0f * str[0] / 64.0f;
        if (out_size > 1) out[1] = srg[0] / 64.0f;
    }
}

extern "C" void kernel_launch(void* const* d_in, const int* in_sizes, int n_in,
                              void* d_out, int out_size) {
    const float* hf  = (const float*)d_in[0];   // (8,1024,768)
    const float* Psi = (const float*)d_in[1];   // (8,1024,64)
    const float* im  = (const float*)d_in[2];   // (8,3,32,32)
    float* out = (float*)d_out;

    cudaFuncSetAttribute(gemm_mma_kernel, cudaFuncAttributeMaxDynamicSharedMemorySize, SM_TOTAL);

    zero_kernel<<<2048, 256>>>();
    split_kernel<<<MM / 8, 256>>>(hf);
    gemm_mma_kernel<<<NPAIRS, 256, SM_TOTAL>>>();
    topk_kernel<<<MM, 256>>>();
    feat_deg_kernel<<<(MM * KF) / 256, 256>>>();
    pixel_adj_kernel<<<BSZ * HW, 256>>>(im);
    pixel_deg_kernel<<<MM / 8, 256>>>();
    drs_kernel<<<MM / 256, 256>>>();
    gP_feat_kernel<<<(MM * KF) / 4, 256>>>(Psi);
    gP_pix_kernel<<<MM, 64>>>(Psi);
    R_kernel<<<MM / 128, 256>>>(Psi);
    final_kernel<<<1, 256>>>(out, out_size);
}

// round 10
// speedup vs baseline: 2.7874x; 1.0044x over previous
#include <cuda_runtime.h>
#include <cuda_bf16.h>
#include <math.h>
#include <stdint.h>

// Problem constants
#define MM   8192        // bs*n
#define DD   768         // feature dim
#define KD   64          // Psi dim
#define KF   32          // feature top-k
#define HW   1024        // pixels per image
#define BSZ  8           // batch

// GEMM tiling (mma.sync bf16 path, family-portable)
#define TB      128                    // output tile 128x128
#define NTILE   (MM/TB)                // 64
#define NPAIRS  (NTILE*(NTILE+1)/2)    // 2080
#define KCH     64                     // K elems per chunk
#define NCHUNK  (DD/KCH)               // 12
#define LDW     72                     // smem row stride in bf16 (64 + 8 pad)
#define TILEB   (128*LDW*2)            // 18432 B per operand tile
#define STAGEB  (4*TILEB)              // 73728 B per stage (Ahi,Alo,Bhi,Blo)
#define SM_TOTAL (2*STAGEB)            // 147456 B dynamic smem

// -------- device scratch (static, no runtime alloc) --------
__device__ __nv_bfloat16 g_Xhi[(size_t)MM*DD];   // 12.6 MB
__device__ __nv_bfloat16 g_Xlo[(size_t)MM*DD];   // 12.6 MB
__device__ float g_A[(size_t)MM*MM];             // clamped sim matrix (268 MB)
__device__ float g_topv[MM*KF];
__device__ int   g_topi[MM*KF];
__device__ float g_deg[MM];
__device__ float g_drs[MM];
__device__ unsigned int g_adjb[(size_t)BSZ*HW*(HW/32)];  // pixel adjacency bitmask (1 MB)
__device__ float g_deg2[MM];
__device__ float g_drs2[MM];
__device__ float g_gP[MM*KD];
__device__ float g_R[KD*KD];

// ================= helpers =================
__device__ __forceinline__ uint32_t smem_u32(const void* p) {
    uint32_t a;
    asm("{ .reg .u64 t; cvta.to.shared.u64 t, %1; cvt.u32.u64 %0, t; }" : "=r"(a) : "l"(p));
    return a;
}
__device__ __forceinline__ void ldm4(uint32_t* r, uint32_t addr) {
    asm volatile("ldmatrix.sync.aligned.m8n8.x4.shared.b16 {%0,%1,%2,%3}, [%4];"
        : "=r"(r[0]), "=r"(r[1]), "=r"(r[2]), "=r"(r[3]) : "r"(addr));
}
__device__ __forceinline__ void mma_bf16(float* d, const uint32_t* a, uint32_t b0, uint32_t b1) {
    asm volatile("mma.sync.aligned.m16n8k16.row.col.f32.bf16.bf16.f32 "
        "{%0,%1,%2,%3}, {%4,%5,%6,%7}, {%8,%9}, {%0,%1,%2,%3};"
        : "+f"(d[0]), "+f"(d[1]), "+f"(d[2]), "+f"(d[3])
        : "r"(a[0]), "r"(a[1]), "r"(a[2]), "r"(a[3]), "r"(b0), "r"(b1));
}
__device__ __forceinline__ void cpasync16(uint32_t dst, const void* src) {
    asm volatile("cp.async.cg.shared.global [%0], [%1], 16;" :: "r"(dst), "l"(src));
}
#define CP_COMMIT() asm volatile("cp.async.commit_group;" ::: "memory")
#define CP_WAIT1()  asm volatile("cp.async.wait_group 1;" ::: "memory")
#define CP_WAIT0()  asm volatile("cp.async.wait_group 0;" ::: "memory")

// -------- zero scratch that accumulates --------
__global__ void zero_kernel() {
    int idx = blockIdx.x * blockDim.x + threadIdx.x;
    int n   = gridDim.x * blockDim.x;
    for (int i = idx; i < MM; i += n) { g_deg[i] = 0.f; g_deg2[i] = 0.f; }
    for (int i = idx; i < MM*KD; i += n) g_gP[i] = 0.f;
    for (int i = idx; i < KD*KD; i += n) g_R[i] = 0.f;
    for (int i = idx; i < (int)((size_t)BSZ*HW*(HW/32)); i += n) g_adjb[i] = 0u;
}

// -------- normalize + bf16 split (1 warp / row) --------
__global__ void split_kernel(const float* __restrict__ hf) {
    int row  = blockIdx.x * 8 + (threadIdx.x >> 5);
    int lane = threadIdx.x & 31;
    const float* x = hf + (size_t)row * DD;
    float s = 0.f;
    for (int k = lane; k < DD; k += 32) { float v = x[k]; s += v * v; }
    #pragma unroll
    for (int o = 16; o > 0; o >>= 1) s += __shfl_xor_sync(0xffffffffu, s, o);
    float inv = 1.0f / sqrtf(s);
    for (int k = lane; k < DD; k += 32) {
        float v = x[k] * inv;
        __nv_bfloat16 hi = __float2bfloat16(v);
        __nv_bfloat16 lo = __float2bfloat16(v - __bfloat162float(hi));
        g_Xhi[(size_t)row * DD + k] = hi;
        g_Xlo[(size_t)row * DD + k] = lo;
    }
}

// -------- bf16-split symmetric GEMM via mma.sync (HMMA) --------
__global__ __launch_bounds__(256) void gemm_mma_kernel() {
    extern __shared__ char sm[];
    uint32_t sb = smem_u32(sm);
    int tid  = threadIdx.x;
    int wid  = tid >> 5;
    int lane = tid & 31;
    int wm   = wid & 3;          // M quadrant (32 rows each)
    int wn   = wid >> 2;         // N half (64 cols each)

    // triangular tile decode (br <= bc)
    int t  = blockIdx.x;
    int bc = (int)((sqrtf(8.0f * (float)t + 1.0f) - 1.0f) * 0.5f);
    while ((bc + 1) * (bc + 2) / 2 <= t) bc++;
    while (bc * (bc + 1) / 2 > t) bc--;
    int br = t - bc * (bc + 1) / 2;

    const char* srcs[4] = {
        (const char*)g_Xhi + (size_t)(br * TB) * (DD * 2),
        (const char*)g_Xlo + (size_t)(br * TB) * (DD * 2),
        (const char*)g_Xhi + (size_t)(bc * TB) * (DD * 2),
        (const char*)g_Xlo + (size_t)(bc * TB) * (DD * 2)
    };

    float acc[2][8][4];
    #pragma unroll
    for (int mt = 0; mt < 2; mt++)
        #pragma unroll
        for (int nt = 0; nt < 8; nt++)
            #pragma unroll
            for (int q = 0; q < 4; q++) acc[mt][nt][q] = 0.f;

    // ldmatrix per-lane addressing: row = lane&15, k-half = lane>>4
    uint32_t rowsel = (uint32_t)(lane & 15);
    uint32_t kbyte  = (uint32_t)((lane >> 4) * 16);   // 8 bf16 = 16 B

    // ---- prologue: load chunk 0 into stage 0 ----
    {
        uint32_t dstb = sb;
        #pragma unroll
        for (int tt = 0; tt < 4; tt++) {
            #pragma unroll
            for (int i = 0; i < 4; i++) {
                int idx = i * 256 + tid;
                int r = idx >> 3, seg = idx & 7;
                cpasync16(dstb + tt * TILEB + r * (LDW * 2) + seg * 16,
                          srcs[tt] + (size_t)r * (DD * 2) + seg * 16);
            }
        }
        CP_COMMIT();
    }

    for (int c = 0; c < NCHUNK; c++) {
        if (c + 1 < NCHUNK) {
            uint32_t dstb = sb + ((c + 1) & 1) * STAGEB;
            int koff = (c + 1) * (KCH * 2);
            #pragma unroll
            for (int tt = 0; tt < 4; tt++) {
                #pragma unroll
                for (int i = 0; i < 4; i++) {
                    int idx = i * 256 + tid;
                    int r = idx >> 3, seg = idx & 7;
                    cpasync16(dstb + tt * TILEB + r * (LDW * 2) + seg * 16,
                              srcs[tt] + (size_t)r * (DD * 2) + koff + seg * 16);
                }
            }
            CP_COMMIT();
            CP_WAIT1();
        } else {
            CP_WAIT0();
        }
        __syncthreads();

        uint32_t stb = sb + (c & 1) * STAGEB;
        uint32_t aHb = stb + 0 * TILEB + (wm * 32 + rowsel) * (LDW * 2) + kbyte;
        uint32_t aLb = stb + 1 * TILEB + (wm * 32 + rowsel) * (LDW * 2) + kbyte;
        uint32_t bHb = stb + 2 * TILEB + (wn * 64 + rowsel) * (LDW * 2) + kbyte;
        uint32_t bLb = stb + 3 * TILEB + (wn * 64 + rowsel) * (LDW * 2) + kbyte;

        #pragma unroll
        for (int ks = 0; ks < 4; ks++) {
            uint32_t kb = ks * 32;     // 16 bf16 per k-step
            uint32_t aH[2][4], aL[2][4], bH[4][4], bL[4][4];
            #pragma unroll
            for (int mt = 0; mt < 2; mt++) {
                ldm4(aH[mt], aHb + mt * (16 * LDW * 2) + kb);
                ldm4(aL[mt], aLb + mt * (16 * LDW * 2) + kb);
            }
            #pragma unroll
            for (int np = 0; np < 4; np++) {
                ldm4(bH[np], bHb + np * (16 * LDW * 2) + kb);
                ldm4(bL[np], bLb + np * (16 * LDW * 2) + kb);
            }
            #pragma unroll
            for (int mt = 0; mt < 2; mt++) {
                #pragma unroll
                for (int nt = 0; nt < 8; nt++) {
                    int np = nt >> 1, od = nt & 1;
                    mma_bf16(acc[mt][nt], aH[mt], bH[np][od], bH[np][od + 2]);
                    mma_bf16(acc[mt][nt], aH[mt], bL[np][od], bL[np][od + 2]);
                    mma_bf16(acc[mt][nt], aL[mt], bH[np][od], bH[np][od + 2]);
                }
            }
        }
        __syncthreads();
    }

    // ---- epilogue: stage tile in smem, clamp+diag, coalesced direct+mirror ----
    float* ep = (float*)sm;            // [128][129] = 66048 B, fits in stage mem
    #pragma unroll
    for (int mt = 0; mt < 2; mt++) {
        #pragma unroll
        for (int nt = 0; nt < 8; nt++) {
            int r0 = wm * 32 + mt * 16 + (lane >> 2);
            int c0 = wn * 64 + nt * 8 + (lane & 3) * 2;
            ep[r0 * 129 + c0]           = acc[mt][nt][0];
            ep[r0 * 129 + c0 + 1]       = acc[mt][nt][1];
            ep[(r0 + 8) * 129 + c0]     = acc[mt][nt][2];
            ep[(r0 + 8) * 129 + c0 + 1] = acc[mt][nt][3];
        }
    }
    __syncthreads();

    // direct rows (coalesced)
    #pragma unroll
    for (int i = 0; i < 64; i++) {
        int idx = i * 256 + tid;
        int r = idx >> 7, cc = idx & 127;
        int ig = br * TB + r, jg = bc * TB + cc;
        float v = ep[r * 129 + cc];
        v = (ig == jg) ? 0.0f : fmaxf(v, 0.0f);
        g_A[(size_t)ig * MM + jg] = v;
    }
    // mirror rows (transposed read from smem, coalesced write)
    if (br != bc) {
        #pragma unroll
        for (int i = 0; i < 64; i++) {
            int idx = i * 256 + tid;
            int cc = idx >> 7, r = idx & 127;
            float v = ep[r * 129 + cc];
            v = fmaxf(v, 0.0f);
            g_A[(size_t)(bc * TB + cc) * MM + br * TB + r] = v;
        }
    }
}

// -------- per-row top-32: warp-autonomous partial top-32 + 8-way merge --------
// Warp w owns rows slice [w*1024, (w+1)*1024). Each warp produces its own
// top-32 list (no block syncs in the loop: owner-lane marks/rescans touch only
// self-written smem). Lists are emitted in (value desc, index asc) order; a
// single-warp 8-way merge preserves the exact global jax tie-rule.
__global__ __launch_bounds__(256) void topk_kernel() {
    int row = blockIdx.x;
    __shared__ float s[MM];                 // 32 KB row copy
    __shared__ float lv[8][KF];
    __shared__ int   li_[8][KF];
    int tid  = threadIdx.x;
    int wid  = tid >> 5, lane = tid & 31;
    const float* arow = g_A + (size_t)row * MM;
    int base = wid << 10;                   // warp's 1024-elem slice

    // load own slice + per-thread top-2 (thread owns j = base + lane + 32*i)
    float v1 = -1.0f, v2 = -1.0f; int i1 = MM, i2 = MM;
    #pragma unroll 8
    for (int i = 0; i < 32; i++) {
        int j = base + lane + (i << 5);
        float v = arow[j];
        s[j] = v;
        if (v > v1)      { v2 = v1; i2 = i1; v1 = v; i1 = j; }
        else if (v > v2) { v2 = v;  i2 = j; }
    }
    int cnt = 2;

    for (int it = 0; it < KF; it++) {
        float v = v1; int idx = i1;
        #pragma unroll
        for (int o = 16; o > 0; o >>= 1) {
            float ov = __shfl_xor_sync(0xffffffffu, v, o);
            int   oi = __shfl_xor_sync(0xffffffffu, idx, o);
            if (ov > v || (ov == v && oi < idx)) { v = ov; idx = oi; }
        }
        if (lane == 0) { lv[wid][it] = v; li_[wid][it] = idx; }
        int owner = (idx - base) & 31;
        if (lane == owner) {
            s[idx] = -1.0f;
            if (cnt == 2) { v1 = v2; i1 = i2; cnt = 1; }
            else {
                v1 = -1.0f; i1 = MM; v2 = -1.0f; i2 = MM;
                #pragma unroll 8
                for (int i = 0; i < 32; i++) {
                    int j = base + lane + (i << 5);
                    float vv = s[j];
                    if (vv > v1)      { v2 = v1; i2 = i1; v1 = vv; i1 = j; }
                    else if (vv > v2) { v2 = vv; i2 = j; }
                }
                cnt = 2;
            }
        }
    }
    __syncthreads();

    // 8-way merge by warp 0 (lanes 0-7 hold list heads, lanes 8-31 sentinels)
    if (wid == 0) {
        int head = 0;
        float hv = (lane < 8) ? lv[lane][0]  : -2.0f;
        int   hi = (lane < 8) ? li_[lane][0] : MM;
        for (int it = 0; it < KF; it++) {
            float v = hv; int idx = hi;
            #pragma unroll
            for (int o = 16; o > 0; o >>= 1) {
                float ov = __shfl_xor_sync(0xffffffffu, v, o);
                int   oi = __shfl_xor_sync(0xffffffffu, idx, o);
                if (ov > v || (ov == v && oi < idx)) { v = ov; idx = oi; }
            }
            if (lane == 0) {
                g_topv[row * KF + it] = v;
                g_topi[row * KF + it] = idx;
            }
            if (lane < 8 && hi == idx) {        // unique: idx is globally unique
                head++;
                hv = (head < KF) ? lv[lane][head]  : -2.0f;
                hi = (head < KF) ? li_[lane][head] : MM;
            }
        }
    }
}

// -------- feature degrees --------
__global__ void feat_deg_kernel() {
    int e = blockIdx.x * blockDim.x + threadIdx.x;
    if (e >= MM * KF) return;
    int i = e >> 5; int j = g_topi[e]; float v = g_topv[e];
    atomicAdd(&g_deg[i], 0.5f * v);
    atomicAdd(&g_deg[j], 0.5f * v);
}

// -------- pixel adjacency (bitmask) --------
__global__ __launch_bounds__(256) void pixel_adj_kernel(const float* __restrict__ im) {
    int blk = blockIdx.x; int b = blk >> 10; int i = blk & 1023;
    int tid = threadIdx.x;
    __shared__ float sf[3][HW];
    __shared__ float sd[HW];
    __shared__ float bv[256];
    __shared__ int   bi[256];
    for (int idx = tid; idx < 3 * HW; idx += 256) {
        int c = idx >> 10; int j = idx & 1023;
        sf[c][j] = (im[((size_t)b * 3 + c) * HW + j] + 1.0f) * 0.5f;
    }
    __syncthreads();
    float xi = (float)(i & 31) * (1.0f / 31.0f);
    float yi = (float)(i >> 5) * (1.0f / 31.0f);
    float f0i = sf[0][i], f1i = sf[1][i], f2i = sf[2][i];

    for (int cfg = 0; cfg < 2; cfg++) {
        float dw = (cfg == 0) ? 2.0f : 0.1f;
        float xiw = xi * dw, yiw = yi * dw;
        float sqi = f0i*f0i + f1i*f1i + f2i*f2i + xiw*xiw + yiw*yiw;
        for (int j = tid; j < HW; j += 256) {
            float xj = (float)(j & 31) * (1.0f / 31.0f) * dw;
            float yj = (float)(j >> 5) * (1.0f / 31.0f) * dw;
            float f0 = sf[0][j], f1 = sf[1][j], f2 = sf[2][j];
            float sqj = f0*f0 + f1*f1 + f2*f2 + xj*xj + yj*yj;
            float dot = f0i*f0 + f1i*f1 + f2i*f2 + xiw*xj + yiw*yj;
            sd[j] = sqi + sqj - 2.0f * dot;
        }
        __syncthreads();
        if (tid == 0) sd[i] = 3.0e38f;
        __syncthreads();
        for (int it = 0; it < 10; it++) {
            float best = 3.0e38f; int bidx = HW;
            for (int j = tid; j < HW; j += 256) {
                float v = sd[j];
                if (v < best) { best = v; bidx = j; }
            }
            bv[tid] = best; bi[tid] = bidx;
            __syncthreads();
            for (int s2 = 128; s2 > 0; s2 >>= 1) {
                if (tid < s2) {
                    if (bv[tid+s2] < bv[tid] || (bv[tid+s2] == bv[tid] && bi[tid+s2] < bi[tid])) {
                        bv[tid] = bv[tid+s2]; bi[tid] = bi[tid+s2];
                    }
                }
                __syncthreads();
            }
            if (tid == 0) {
                int js = bi[0];
                atomicOr(&g_adjb[((size_t)b * HW + i)  * (HW/32) + (js >> 5)], 1u << (js & 31));
                atomicOr(&g_adjb[((size_t)b * HW + js) * (HW/32) + (i  >> 5)], 1u << (i  & 31));
                sd[js] = 3.0e38f;
            }
            __syncthreads();
        }
        __syncthreads();
    }
}

// -------- pixel degrees (1 warp / row, popcount) --------
__global__ void pixel_deg_kernel() {
    int g    = blockIdx.x * 8 + (threadIdx.x >> 5);
    int lane = threadIdx.x & 31;
    unsigned int w = g_adjb[(size_t)g * (HW/32) + lane];
    float s = (float)__popc(w);
    #pragma unroll
    for (int o = 16; o > 0; o >>= 1) s += __shfl_xor_sync(0xffffffffu, s, o);
    if (lane == 0) g_deg2[g] = s;
}

__global__ void drs_kernel() {
    int i = blockIdx.x * 256 + threadIdx.x;
    if (i < MM) {
        g_drs[i]  = 1.0f / sqrtf(g_deg[i]);
        g_drs2[i] = 1.0f / sqrtf(g_deg2[i]);
    }
}

// -------- gP += feature-gram @ Psi --------
__global__ __launch_bounds__(256) void gP_feat_kernel(const float* __restrict__ Psi) {
    int e = blockIdx.x * 4 + (threadIdx.x >> 6);
    int a = threadIdx.x & 63;
    int i = e >> 5; int j = g_topi[e]; float v = g_topv[e];
    float w = 0.5f * v * g_drs[i] * g_drs[j];
    atomicAdd(&g_gP[i * KD + a], w * Psi[(size_t)j * KD + a]);
    atomicAdd(&g_gP[j * KD + a], w * Psi[(size_t)i * KD + a]);
}

// -------- gP += 0.05 * pixel-gram @ Psi (bitmask iteration) --------
__global__ void gP_pix_kernel(const float* __restrict__ Psi) {
    int g = blockIdx.x; int b = g >> 10; int a = threadIdx.x;   // 64 threads
    __shared__ unsigned int sw[HW/32];
    if (a < HW/32) sw[a] = g_adjb[(size_t)g * (HW/32) + a];
    __syncthreads();
    float wb  = 0.05f * g_drs2[g];
    float acc = 0.f;
    int base  = b * HW;
    #pragma unroll 4
    for (int w = 0; w < HW/32; w++) {
        unsigned int m = sw[w];
        while (m) {
            int bpos = __ffs(m) - 1;
            m &= m - 1;
            int j = base + w * 32 + bpos;
            acc += wb * g_drs2[j] * Psi[(size_t)j * KD + a];
        }
    }
    g_gP[g * KD + a] += acc;
}

// -------- R = Psi^T gP --------
__global__ __launch_bounds__(256) void R_kernel(const float* __restrict__ Psi) {
    __shared__ float sp[KD], sg[KD];
    int tid = threadIdx.x;
    int a = tid >> 2; int b0 = (tid & 3) * 16;
    float acc[16];
    #pragma unroll
    for (int bb = 0; bb < 16; bb++) acc[bb] = 0.f;
    int i0 = blockIdx.x * 128;
    for (int i = i0; i < i0 + 128; i++) {
        if (tid < KD) { sp[tid] = Psi[(size_t)i * KD + tid]; sg[tid] = g_gP[i * KD + tid]; }
        __syncthreads();
        float pa = sp[a];
        #pragma unroll
        for (int bb = 0; bb < 16; bb++) acc[bb] += pa * sg[b0 + bb];
        __syncthreads();
    }
    #pragma unroll
    for (int bb = 0; bb < 16; bb++) atomicAdd(&g_R[a * 64 + b0 + bb], acc[bb]);
}

// -------- final scalars --------
__global__ void final_kernel(float* out, int out_size) {
    __shared__ float str[256], srg[256];
    int tid = threadIdx.x;
    float tr = 0.f, rg = 0.f;
    for (int idx = tid; idx < KD * KD; idx += 256) {
        int a = idx >> 6, bcol = idx & 63;
        float v = g_R[idx];
        if (a == bcol) tr += v;
        else if (bcol > a) { float x = 10.0f * v; rg += x * x; }
    }
    str[tid] = tr; srg[tid] = rg;
    __syncthreads();
    for (int s = 128; s > 0; s >>= 1) {
        if (tid < s) { str[tid] += str[tid + s]; srg[tid] += srg[tid + s]; }
        __syncthreads();
    }
    for (int i = tid; i < out_size; i += 256) out[i] = 0.0f;
    __syncthreads();
    if (tid == 0) {
        if (out_size > 0) out[0] = -10.0f * str[0] / 64.0f;
        if (out_size > 1) out[1] = srg[0] / 64.0f;
    }
}

extern "C" void kernel_launch(void* const* d_in, const int* in_sizes, int n_in,
                              void* d_out, int out_size) {
    const float* hf  = (const float*)d_in[0];   // (8,1024,768)
    const float* Psi = (const float*)d_in[1];   // (8,1024,64)
    const float* im  = (const float*)d_in[2];   // (8,3,32,32)
    float* out = (float*)d_out;

    cudaFuncSetAttribute(gemm_mma_kernel, cudaFuncAttributeMaxDynamicSharedMemorySize, SM_TOTAL);

    zero_kernel<<<2048, 256>>>();
    split_kernel<<<MM / 8, 256>>>(hf);
    gemm_mma_kernel<<<NPAIRS, 256, SM_TOTAL>>>();
    topk_kernel<<<MM, 256>>>();
    feat_deg_kernel<<<(MM * KF) / 256, 256>>>();
    pixel_adj_kernel<<<BSZ * HW, 256>>>(im);
    pixel_deg_kernel<<<MM / 8, 256>>>();
    drs_kernel<<<MM / 256, 256>>>();
    gP_feat_kernel<<<(MM * KF) / 4, 256>>>(Psi);
    gP_pix_kernel<<<MM, 64>>>(Psi);
    R_kernel<<<MM / 128, 256>>>(Psi);
    final_kernel<<<1, 256>>>(out, out_size);
}

// round 11
// speedup vs baseline: 3.0941x; 1.1100x over previous
#include <cuda_runtime.h>
#include <cuda_bf16.h>
#include <math.h>
#include <stdint.h>

// Problem constants
#define MM   8192        // bs*n
#define DD   768         // feature dim
#define KD   64          // Psi dim
#define KF   32          // feature top-k
#define HW   1024        // pixels per image
#define BSZ  8           // batch

// GEMM tiling (mma.sync bf16 path, family-portable)
#define TB      128                    // output tile 128x128
#define NTILE   (MM/TB)                // 64
#define NPAIRS  (NTILE*(NTILE+1)/2)    // 2080
#define KCH     64                     // K elems per chunk
#define NCHUNK  (DD/KCH)               // 12
#define LDW     72                     // smem row stride in bf16 (64 + 8 pad)
#define TILEB   (128*LDW*2)            // 18432 B per operand tile
#define STAGEB  (4*TILEB)              // 73728 B per stage (Ahi,Alo,Bhi,Blo)
#define SM_TOTAL (2*STAGEB)            // 147456 B dynamic smem

// -------- device scratch (static, no runtime alloc) --------
__device__ __nv_bfloat16 g_Xhi[(size_t)MM*DD];   // 12.6 MB
__device__ __nv_bfloat16 g_Xlo[(size_t)MM*DD];   // 12.6 MB
__device__ float g_A[(size_t)MM*MM];             // clamped sim matrix (268 MB)
__device__ float g_topv[MM*KF];
__device__ int   g_topi[MM*KF];
__device__ float g_deg[MM];
__device__ float g_drs[MM];
__device__ unsigned int g_adjb[(size_t)BSZ*HW*(HW/32)];  // pixel adjacency bitmask (1 MB)
__device__ float g_deg2[MM];
__device__ float g_drs2[MM];
__device__ float g_gP[MM*KD];
__device__ float g_R[KD*KD];

// ================= helpers =================
__device__ __forceinline__ uint32_t smem_u32(const void* p) {
    uint32_t a;
    asm("{ .reg .u64 t; cvta.to.shared.u64 t, %1; cvt.u32.u64 %0, t; }" : "=r"(a) : "l"(p));
    return a;
}
__device__ __forceinline__ void ldm4(uint32_t* r, uint32_t addr) {
    asm volatile("ldmatrix.sync.aligned.m8n8.x4.shared.b16 {%0,%1,%2,%3}, [%4];"
        : "=r"(r[0]), "=r"(r[1]), "=r"(r[2]), "=r"(r[3]) : "r"(addr));
}
__device__ __forceinline__ void mma_bf16(float* d, const uint32_t* a, uint32_t b0, uint32_t b1) {
    asm volatile("mma.sync.aligned.m16n8k16.row.col.f32.bf16.bf16.f32 "
        "{%0,%1,%2,%3}, {%4,%5,%6,%7}, {%8,%9}, {%0,%1,%2,%3};"
        : "+f"(d[0]), "+f"(d[1]), "+f"(d[2]), "+f"(d[3])
        : "r"(a[0]), "r"(a[1]), "r"(a[2]), "r"(a[3]), "r"(b0), "r"(b1));
}
__device__ __forceinline__ void cpasync16(uint32_t dst, const void* src) {
    asm volatile("cp.async.cg.shared.global [%0], [%1], 16;" :: "r"(dst), "l"(src));
}
#define CP_COMMIT() asm volatile("cp.async.commit_group;" ::: "memory")
#define CP_WAIT1()  asm volatile("cp.async.wait_group 1;" ::: "memory")
#define CP_WAIT0()  asm volatile("cp.async.wait_group 0;" ::: "memory")

// -------- zero scratch that accumulates --------
__global__ void zero_kernel() {
    int idx = blockIdx.x * blockDim.x + threadIdx.x;
    int n   = gridDim.x * blockDim.x;
    for (int i = idx; i < MM; i += n) { g_deg[i] = 0.f; g_deg2[i] = 0.f; }
    for (int i = idx; i < MM*KD; i += n) g_gP[i] = 0.f;
    for (int i = idx; i < KD*KD; i += n) g_R[i] = 0.f;
    for (int i = idx; i < (int)((size_t)BSZ*HW*(HW/32)); i += n) g_adjb[i] = 0u;
}

// -------- normalize + bf16 split (1 warp / row) --------
__global__ void split_kernel(const float* __restrict__ hf) {
    int row  = blockIdx.x * 8 + (threadIdx.x >> 5);
    int lane = threadIdx.x & 31;
    const float* x = hf + (size_t)row * DD;
    float s = 0.f;
    for (int k = lane; k < DD; k += 32) { float v = x[k]; s += v * v; }
    #pragma unroll
    for (int o = 16; o > 0; o >>= 1) s += __shfl_xor_sync(0xffffffffu, s, o);
    float inv = 1.0f / sqrtf(s);
    for (int k = lane; k < DD; k += 32) {
        float v = x[k] * inv;
        __nv_bfloat16 hi = __float2bfloat16(v);
        __nv_bfloat16 lo = __float2bfloat16(v - __bfloat162float(hi));
        g_Xhi[(size_t)row * DD + k] = hi;
        g_Xlo[(size_t)row * DD + k] = lo;
    }
}

// -------- bf16-split symmetric GEMM via mma.sync (HMMA) --------
__global__ __launch_bounds__(256) void gemm_mma_kernel() {
    extern __shared__ char sm[];
    uint32_t sb = smem_u32(sm);
    int tid  = threadIdx.x;
    int wid  = tid >> 5;
    int lane = tid & 31;
    int wm   = wid & 3;          // M quadrant (32 rows each)
    int wn   = wid >> 2;         // N half (64 cols each)

    // triangular tile decode (br <= bc)
    int t  = blockIdx.x;
    int bc = (int)((sqrtf(8.0f * (float)t + 1.0f) - 1.0f) * 0.5f);
    while ((bc + 1) * (bc + 2) / 2 <= t) bc++;
    while (bc * (bc + 1) / 2 > t) bc--;
    int br = t - bc * (bc + 1) / 2;

    const char* srcs[4] = {
        (const char*)g_Xhi + (size_t)(br * TB) * (DD * 2),
        (const char*)g_Xlo + (size_t)(br * TB) * (DD * 2),
        (const char*)g_Xhi + (size_t)(bc * TB) * (DD * 2),
        (const char*)g_Xlo + (size_t)(bc * TB) * (DD * 2)
    };

    float acc[2][8][4];
    #pragma unroll
    for (int mt = 0; mt < 2; mt++)
        #pragma unroll
        for (int nt = 0; nt < 8; nt++)
            #pragma unroll
            for (int q = 0; q < 4; q++) acc[mt][nt][q] = 0.f;

    // ldmatrix per-lane addressing: row = lane&15, k-half = lane>>4
    uint32_t rowsel = (uint32_t)(lane & 15);
    uint32_t kbyte  = (uint32_t)((lane >> 4) * 16);   // 8 bf16 = 16 B

    // ---- prologue: load chunk 0 into stage 0 ----
    {
        uint32_t dstb = sb;
        #pragma unroll
        for (int tt = 0; tt < 4; tt++) {
            #pragma unroll
            for (int i = 0; i < 4; i++) {
                int idx = i * 256 + tid;
                int r = idx >> 3, seg = idx & 7;
                cpasync16(dstb + tt * TILEB + r * (LDW * 2) + seg * 16,
                          srcs[tt] + (size_t)r * (DD * 2) + seg * 16);
            }
        }
        CP_COMMIT();
    }

    for (int c = 0; c < NCHUNK; c++) {
        if (c + 1 < NCHUNK) {
            uint32_t dstb = sb + ((c + 1) & 1) * STAGEB;
            int koff = (c + 1) * (KCH * 2);
            #pragma unroll
            for (int tt = 0; tt < 4; tt++) {
                #pragma unroll
                for (int i = 0; i < 4; i++) {
                    int idx = i * 256 + tid;
                    int r = idx >> 3, seg = idx & 7;
                    cpasync16(dstb + tt * TILEB + r * (LDW * 2) + seg * 16,
                              srcs[tt] + (size_t)r * (DD * 2) + koff + seg * 16);
                }
            }
            CP_COMMIT();
            CP_WAIT1();
        } else {
            CP_WAIT0();
        }
        __syncthreads();

        uint32_t stb = sb + (c & 1) * STAGEB;
        uint32_t aHb = stb + 0 * TILEB + (wm * 32 + rowsel) * (LDW * 2) + kbyte;
        uint32_t aLb = stb + 1 * TILEB + (wm * 32 + rowsel) * (LDW * 2) + kbyte;
        uint32_t bHb = stb + 2 * TILEB + (wn * 64 + rowsel) * (LDW * 2) + kbyte;
        uint32_t bLb = stb + 3 * TILEB + (wn * 64 + rowsel) * (LDW * 2) + kbyte;

        #pragma unroll
        for (int ks = 0; ks < 4; ks++) {
            uint32_t kb = ks * 32;     // 16 bf16 per k-step
            uint32_t aH[2][4], aL[2][4], bH[4][4], bL[4][4];
            #pragma unroll
            for (int mt = 0; mt < 2; mt++) {
                ldm4(aH[mt], aHb + mt * (16 * LDW * 2) + kb);
                ldm4(aL[mt], aLb + mt * (16 * LDW * 2) + kb);
            }
            #pragma unroll
            for (int np = 0; np < 4; np++) {
                ldm4(bH[np], bHb + np * (16 * LDW * 2) + kb);
                ldm4(bL[np], bLb + np * (16 * LDW * 2) + kb);
            }
            #pragma unroll
            for (int mt = 0; mt < 2; mt++) {
                #pragma unroll
                for (int nt = 0; nt < 8; nt++) {
                    int np = nt >> 1, od = nt & 1;
                    mma_bf16(acc[mt][nt], aH[mt], bH[np][od], bH[np][od + 2]);
                    mma_bf16(acc[mt][nt], aH[mt], bL[np][od], bL[np][od + 2]);
                    mma_bf16(acc[mt][nt], aL[mt], bH[np][od], bH[np][od + 2]);
                }
            }
        }
        __syncthreads();
    }

    // ---- epilogue: stage tile in smem, clamp+diag, coalesced direct+mirror ----
    float* ep = (float*)sm;            // [128][129] = 66048 B, fits in stage mem
    #pragma unroll
    for (int mt = 0; mt < 2; mt++) {
        #pragma unroll
        for (int nt = 0; nt < 8; nt++) {
            int r0 = wm * 32 + mt * 16 + (lane >> 2);
            int c0 = wn * 64 + nt * 8 + (lane & 3) * 2;
            ep[r0 * 129 + c0]           = acc[mt][nt][0];
            ep[r0 * 129 + c0 + 1]       = acc[mt][nt][1];
            ep[(r0 + 8) * 129 + c0]     = acc[mt][nt][2];
            ep[(r0 + 8) * 129 + c0 + 1] = acc[mt][nt][3];
        }
    }
    __syncthreads();

    // direct rows (coalesced)
    #pragma unroll
    for (int i = 0; i < 64; i++) {
        int idx = i * 256 + tid;
        int r = idx >> 7, cc = idx & 127;
        int ig = br * TB + r, jg = bc * TB + cc;
        float v = ep[r * 129 + cc];
        v = (ig == jg) ? 0.0f : fmaxf(v, 0.0f);
        g_A[(size_t)ig * MM + jg] = v;
    }
    // mirror rows (transposed read from smem, coalesced write)
    if (br != bc) {
        #pragma unroll
        for (int i = 0; i < 64; i++) {
            int idx = i * 256 + tid;
            int cc = idx >> 7, r = idx & 127;
            float v = ep[r * 129 + cc];
            v = fmaxf(v, 0.0f);
            g_A[(size_t)(bc * TB + cc) * MM + br * TB + r] = v;
        }
    }
}

// -------- per-row top-32: shared row + register top-2 cache (R8 version) --------
__global__ __launch_bounds__(256) void topk_kernel() {
    int row = blockIdx.x;
    __shared__ float s[MM];
    __shared__ float wv[8];
    __shared__ int   wi[8];
    __shared__ int   sbi_s;
    int tid = threadIdx.x;
    const float* arow = g_A + (size_t)row * MM;

    float v1 = -1.0f, v2 = -1.0f; int i1 = MM, i2 = MM;
    #pragma unroll 8
    for (int i = 0; i < 32; i++) {
        int j = tid + (i << 8);
        float v = arow[j];
        s[j] = v;
        if (v > v1)      { v2 = v1; i2 = i1; v1 = v; i1 = j; }
        else if (v > v2) { v2 = v;  i2 = j; }
    }
    int cnt = 2;
    __syncthreads();

    for (int it = 0; it < KF; it++) {
        float v = v1; int idx = i1;
        #pragma unroll
        for (int o = 16; o > 0; o >>= 1) {
            float ov = __shfl_xor_sync(0xffffffffu, v, o);
            int   oi = __shfl_xor_sync(0xffffffffu, idx, o);
            if (ov > v || (ov == v && oi < idx)) { v = ov; idx = oi; }
        }
        if ((tid & 31) == 0) { wv[tid >> 5] = v; wi[tid >> 5] = idx; }
        __syncthreads();
        if (tid < 8) {
            float v8 = wv[tid]; int i8 = wi[tid];
            #pragma unroll
            for (int o = 4; o > 0; o >>= 1) {
                float ov = __shfl_xor_sync(0x000000ffu, v8, o);
                int   oi = __shfl_xor_sync(0x000000ffu, i8, o);
                if (ov > v8 || (ov == v8 && oi < i8)) { v8 = ov; i8 = oi; }
            }
            if (tid == 0) {
                g_topv[row * KF + it] = v8;
                g_topi[row * KF + it] = i8;
                sbi_s = i8;
            }
        }
        __syncthreads();
        int win = sbi_s;
        if ((win & 255) == tid) {
            s[win] = -1.0f;
            if (cnt == 2) {
                v1 = v2; i1 = i2; cnt = 1;
            } else {
                v1 = -1.0f; i1 = MM; v2 = -1.0f; i2 = MM;
                #pragma unroll 8
                for (int i = 0; i < 32; i++) {
                    int j = tid + (i << 8);
                    float vv = s[j];
                    if (vv > v1)      { v2 = v1; i2 = i1; v1 = vv; i1 = j; }
                    else if (vv > v2) { v2 = vv; i2 = j; }
                }
                cnt = 2;
            }
        }
    }
}

// -------- feature degrees --------
__global__ void feat_deg_kernel() {
    int e = blockIdx.x * blockDim.x + threadIdx.x;
    if (e >= MM * KF) return;
    int i = e >> 5; int j = g_topi[e]; float v = g_topv[e];
    atomicAdd(&g_deg[i], 0.5f * v);
    atomicAdd(&g_deg[j], 0.5f * v);
}

// -------- pixel adjacency (bitmask) --------
__global__ __launch_bounds__(256) void pixel_adj_kernel(const float* __restrict__ im) {
    int blk = blockIdx.x; int b = blk >> 10; int i = blk & 1023;
    int tid = threadIdx.x;
    __shared__ float sf[3][HW];
    __shared__ float sd[HW];
    __shared__ float bv[256];
    __shared__ int   bi[256];
    for (int idx = tid; idx < 3 * HW; idx += 256) {
        int c = idx >> 10; int j = idx & 1023;
        sf[c][j] = (im[((size_t)b * 3 + c) * HW + j] + 1.0f) * 0.5f;
    }
    __syncthreads();
    float xi = (float)(i & 31) * (1.0f / 31.0f);
    float yi = (float)(i >> 5) * (1.0f / 31.0f);
    float f0i = sf[0][i], f1i = sf[1][i], f2i = sf[2][i];

    for (int cfg = 0; cfg < 2; cfg++) {
        float dw = (cfg == 0) ? 2.0f : 0.1f;
        float xiw = xi * dw, yiw = yi * dw;
        float sqi = f0i*f0i + f1i*f1i + f2i*f2i + xiw*xiw + yiw*yiw;
        for (int j = tid; j < HW; j += 256) {
            float xj = (float)(j & 31) * (1.0f / 31.0f) * dw;
            float yj = (float)(j >> 5) * (1.0f / 31.0f) * dw;
            float f0 = sf[0][j], f1 = sf[1][j], f2 = sf[2][j];
            float sqj = f0*f0 + f1*f1 + f2*f2 + xj*xj + yj*yj;
            float dot = f0i*f0 + f1i*f1 + f2i*f2 + xiw*xj + yiw*yj;
            sd[j] = sqi + sqj - 2.0f * dot;
        }
        __syncthreads();
        if (tid == 0) sd[i] = 3.0e38f;
        __syncthreads();
        for (int it = 0; it < 10; it++) {
            float best = 3.0e38f; int bidx = HW;
            for (int j = tid; j < HW; j += 256) {
                float v = sd[j];
                if (v < best) { best = v; bidx = j; }
            }
            bv[tid] = best; bi[tid] = bidx;
            __syncthreads();
            for (int s2 = 128; s2 > 0; s2 >>= 1) {
                if (tid < s2) {
                    if (bv[tid+s2] < bv[tid] || (bv[tid+s2] == bv[tid] && bi[tid+s2] < bi[tid])) {
                        bv[tid] = bv[tid+s2]; bi[tid] = bi[tid+s2];
                    }
                }
                __syncthreads();
            }
            if (tid == 0) {
                int js = bi[0];
                atomicOr(&g_adjb[((size_t)b * HW + i)  * (HW/32) + (js >> 5)], 1u << (js & 31));
                atomicOr(&g_adjb[((size_t)b * HW + js) * (HW/32) + (i  >> 5)], 1u << (i  & 31));
                sd[js] = 3.0e38f;
            }
            __syncthreads();
        }
        __syncthreads();
    }
}

// -------- pixel degrees (1 warp / row, popcount) --------
__global__ void pixel_deg_kernel() {
    int g    = blockIdx.x * 8 + (threadIdx.x >> 5);
    int lane = threadIdx.x & 31;
    unsigned int w = g_adjb[(size_t)g * (HW/32) + lane];
    float s = (float)__popc(w);
    #pragma unroll
    for (int o = 16; o > 0; o >>= 1) s += __shfl_xor_sync(0xffffffffu, s, o);
    if (lane == 0) g_deg2[g] = s;
}

__global__ void drs_kernel() {
    int i = blockIdx.x * 256 + threadIdx.x;
    if (i < MM) {
        g_drs[i]  = 1.0f / sqrtf(g_deg[i]);
        g_drs2[i] = 1.0f / sqrtf(g_deg2[i]);
    }
}

// -------- gP += feature-gram @ Psi --------
__global__ __launch_bounds__(256) void gP_feat_kernel(const float* __restrict__ Psi) {
    int e = blockIdx.x * 4 + (threadIdx.x >> 6);
    int a = threadIdx.x & 63;
    int i = e >> 5; int j = g_topi[e]; float v = g_topv[e];
    float w = 0.5f * v * g_drs[i] * g_drs[j];
    atomicAdd(&g_gP[i * KD + a], w * Psi[(size_t)j * KD + a]);
    atomicAdd(&g_gP[j * KD + a], w * Psi[(size_t)i * KD + a]);
}

// -------- gP += 0.05 * pixel-gram @ Psi (bitmask iteration) --------
__global__ void gP_pix_kernel(const float* __restrict__ Psi) {
    int g = blockIdx.x; int b = g >> 10; int a = threadIdx.x;   // 64 threads
    __shared__ unsigned int sw[HW/32];
    if (a < HW/32) sw[a] = g_adjb[(size_t)g * (HW/32) + a];
    __syncthreads();
    float wb  = 0.05f * g_drs2[g];
    float acc = 0.f;
    int base  = b * HW;
    #pragma unroll 4
    for (int w = 0; w < HW/32; w++) {
        unsigned int m = sw[w];
        while (m) {
            int bpos = __ffs(m) - 1;
            m &= m - 1;
            int j = base + w * 32 + bpos;
            acc += wb * g_drs2[j] * Psi[(size_t)j * KD + a];
        }
    }
    g_gP[g * KD + a] += acc;
}

// -------- R = Psi^T gP --------
__global__ __launch_bounds__(256) void R_kernel(const float* __restrict__ Psi) {
    __shared__ float sp[KD], sg[KD];
    int tid = threadIdx.x;
    int a = tid >> 2; int b0 = (tid & 3) * 16;
    float acc[16];
    #pragma unroll
    for (int bb = 0; bb < 16; bb++) acc[bb] = 0.f;
    int i0 = blockIdx.x * 128;
    for (int i = i0; i < i0 + 128; i++) {
        if (tid < KD) { sp[tid] = Psi[(size_t)i * KD + tid]; sg[tid] = g_gP[i * KD + tid]; }
        __syncthreads();
        float pa = sp[a];
        #pragma unroll
        for (int bb = 0; bb < 16; bb++) acc[bb] += pa * sg[b0 + bb];
        __syncthreads();
    }
    #pragma unroll
    for (int bb = 0; bb < 16; bb++) atomicAdd(&g_R[a * 64 + b0 + bb], acc[bb]);
}

// -------- final scalars --------
__global__ void final_kernel(float* out, int out_size) {
    __shared__ float str[256], srg[256];
    int tid = threadIdx.x;
    float tr = 0.f, rg = 0.f;
    for (int idx = tid; idx < KD * KD; idx += 256) {
        int a = idx >> 6, bcol = idx & 63;
        float v = g_R[idx];
        if (a == bcol) tr += v;
        else if (bcol > a) { float x = 10.0f * v; rg += x * x; }
    }
    str[tid] = tr; srg[tid] = rg;
    __syncthreads();
    for (int s = 128; s > 0; s >>= 1) {
        if (tid < s) { str[tid] += str[tid + s]; srg[tid] += srg[tid + s]; }
        __syncthreads();
    }
    for (int i = tid; i < out_size; i += 256) out[i] = 0.0f;
    __syncthreads();
    if (tid == 0) {
        if (out_size > 0) out[0] = -10.0f * str[0] / 64.0f;
        if (out_size > 1) out[1] = srg[0] / 64.0f;
    }
}

extern "C" void kernel_launch(void* const* d_in, const int* in_sizes, int n_in,
                              void* d_out, int out_size) {
    const float* hf  = (const float*)d_in[0];   // (8,1024,768)
    const float* Psi = (const float*)d_in[1];   // (8,1024,64)
    const float* im  = (const float*)d_in[2];   // (8,3,32,32)
    float* out = (float*)d_out;

    cudaFuncSetAttribute(gemm_mma_kernel, cudaFuncAttributeMaxDynamicSharedMemorySize, SM_TOTAL);

    zero_kernel<<<2048, 256>>>();
    split_kernel<<<MM / 8, 256>>>(hf);
    gemm_mma_kernel<<<NPAIRS, 256, SM_TOTAL>>>();
    topk_kernel<<<MM, 256>>>();
    feat_deg_kernel<<<(MM * KF) / 256, 256>>>();
    pixel_adj_kernel<<<BSZ * HW, 256>>>(im);
    pixel_deg_kernel<<<MM / 8, 256>>>();
    drs_kernel<<<MM / 256, 256>>>();
    gP_feat_kernel<<<(MM * KF) / 4, 256>>>(Psi);
    gP_pix_kernel<<<MM, 64>>>(Psi);
    R_kernel<<<MM / 128, 256>>>(Psi);
    final_kernel<<<1, 256>>>(out, out_size);
}